// round 1
// baseline (speedup 1.0000x reference)
#include <cuda_runtime.h>

#define Bb 2
#define Ss 2048
#define Dd 2048
#define KVH 8
#define QPG 4
#define HD 64
#define Mtot (Bb*Ss)            // 4096
#define NQ (KVH*QPG*HD)         // 2048
#define NKV (KVH*HD)            // 512
#define NTOT (NQ + 2*NKV)       // 3072

// ---------------- scratch (module-load static, no runtime allocs) ----------
__device__ float g_qkv[(size_t)Mtot * NTOT];                 // 50 MB
__device__ float g_q[(size_t)Bb*KVH*QPG*Ss*HD];              // 33.5 MB  [b][gp][s][h]
__device__ float g_k[(size_t)Bb*KVH*Ss*HD];                  // 8.4 MB   [b][g][s][h]
__device__ float g_v[(size_t)Bb*KVH*Ss*HD];                  // 8.4 MB
__device__ float g_attn[(size_t)Mtot * NQ];                  // 33.5 MB  [b][s][gp*64+h]

// ---------------- GEMM: C[M rows][ldc] (+= block) = A[M][K] @ W[N][K]^T ----
// Both operands K-contiguous (NT). 128x128x8 tile, 256 threads, 8x8 microtile.
__global__ __launch_bounds__(256) void gemm_nt(
    const float* __restrict__ A,
    const float* __restrict__ W0, const float* __restrict__ W1,
    const float* __restrict__ W2,
    int nb0, int nb1,
    float* __restrict__ C, int Kdim, int ldc)
{
    const int BM = 128, BN = 128, BK = 8;
    __shared__ float As[BK][BM];
    __shared__ float Bs[BK][BN];

    int nb = blockIdx.x, mb = blockIdx.y;
    const float* W;
    if (nb < nb0)            W = W0 + (size_t)nb * BN * Kdim;
    else if (nb < nb0 + nb1) W = W1 + (size_t)(nb - nb0) * BN * Kdim;
    else                     W = W2 + (size_t)(nb - nb0 - nb1) * BN * Kdim;
    const float* Ab = A + (size_t)mb * BM * Kdim;

    int tid = threadIdx.x;
    int tm = tid >> 4, tn = tid & 15;
    int lr = tid >> 1;              // 0..127 (row within tile)
    int lc = (tid & 1) * 4;         // 0 or 4 (k offset)

    float acc[8][8];
#pragma unroll
    for (int i = 0; i < 8; i++)
#pragma unroll
        for (int j = 0; j < 8; j++) acc[i][j] = 0.f;

    for (int k0 = 0; k0 < Kdim; k0 += BK) {
        float4 av = *(const float4*)(Ab + (size_t)lr * Kdim + k0 + lc);
        float4 bv = *(const float4*)(W  + (size_t)lr * Kdim + k0 + lc);
        As[lc + 0][lr] = av.x; As[lc + 1][lr] = av.y;
        As[lc + 2][lr] = av.z; As[lc + 3][lr] = av.w;
        Bs[lc + 0][lr] = bv.x; Bs[lc + 1][lr] = bv.y;
        Bs[lc + 2][lr] = bv.z; Bs[lc + 3][lr] = bv.w;
        __syncthreads();
#pragma unroll
        for (int kk = 0; kk < BK; kk++) {
            float a[8], b[8];
            *(float4*)(a)     = *(const float4*)&As[kk][tm * 8];
            *(float4*)(a + 4) = *(const float4*)&As[kk][tm * 8 + 4];
            *(float4*)(b)     = *(const float4*)&Bs[kk][tn * 8];
            *(float4*)(b + 4) = *(const float4*)&Bs[kk][tn * 8 + 4];
#pragma unroll
            for (int i = 0; i < 8; i++)
#pragma unroll
                for (int j = 0; j < 8; j++)
                    acc[i][j] = fmaf(a[i], b[j], acc[i][j]);
        }
        __syncthreads();
    }

    int crow = mb * BM + tm * 8;
    int ccol = nb * BN + tn * 8;
#pragma unroll
    for (int i = 0; i < 8; i++) {
        float4 v0 = make_float4(acc[i][0], acc[i][1], acc[i][2], acc[i][3]);
        float4 v1 = make_float4(acc[i][4], acc[i][5], acc[i][6], acc[i][7]);
        *(float4*)(C + (size_t)(crow + i) * ldc + ccol)     = v0;
        *(float4*)(C + (size_t)(crow + i) * ldc + ccol + 4) = v1;
    }
}

// ---------------- RMSNorm + partial RoPE + scatter to head layouts --------
// One block per (b,s) row; each warp processes 64-dim head vectors.
// Lane l owns dims l and l+32 (the RoPE rotation pair; cos/sin identical).
__global__ __launch_bounds__(256) void norm_rope(
    const float* __restrict__ qn, const float* __restrict__ kn,
    const int* __restrict__ pos_ids)
{
    int m = blockIdx.x;                 // 0..4095
    int b = m / Ss, s = m % Ss;
    int warp = threadIdx.x >> 5, lane = threadIdx.x & 31;
    float pos = (float)pos_ids[s];

    for (int iv = warp; iv < 48; iv += 8) {
        const float* src = g_qkv + (size_t)m * NTOT + iv * 64;
        float x1 = src[lane], x2 = src[lane + 32];
        if (iv < 40) {  // q or k head: rmsnorm + rope
            float ssum = x1 * x1 + x2 * x2;
#pragma unroll
            for (int o = 16; o >= 1; o >>= 1)
                ssum += __shfl_xor_sync(0xffffffffu, ssum, o);
            float inv = rsqrtf(ssum * (1.f / 64.f) + 1e-5f);
            const float* w = (iv < 32) ? qn : kn;
            x1 = x1 * inv * w[lane];
            x2 = x2 * inv * w[lane + 32];
            // inv_freq: 1024^(-l/16) = 2^(-0.625 l) for l<16, else 0
            float invf = (lane < 16) ? exp2f(-0.625f * (float)lane) : 0.f;
            float f = pos * invf;
            float sn, cs;
            __sincosf(f, &sn, &cs);
            // higher precision for safety:
            sn = sinf(f); cs = cosf(f);
            float o1 = x1 * cs - x2 * sn;
            float o2 = x2 * cs + x1 * sn;
            x1 = o1; x2 = o2;
        }
        float* dst;
        if (iv < 32)      dst = g_q + ((size_t)(b * 32 + iv) * Ss + s) * HD;
        else if (iv < 40) dst = g_k + ((size_t)(b * KVH + (iv - 32)) * Ss + s) * HD;
        else              dst = g_v + ((size_t)(b * KVH + (iv - 40)) * Ss + s) * HD;
        dst[lane] = x1;
        dst[lane + 32] = x2;
    }
}

// ---------------- Flash attention: softcap + causal + online softmax ------
// grid (32 qblocks, 64 heads); 256 threads; 64q x 64k tile, 4x4 per thread.
__global__ __launch_bounds__(256) void flash_attn()
{
    int head = blockIdx.y;                    // 0..63  (b*32 + gp)
    int qb = gridDim.x - 1 - blockIdx.x;      // long rows first
    int b = head >> 5, gp = head & 31, g = gp >> 2;

    const float* Qg = g_q + ((size_t)head * Ss + qb * 64) * HD;
    const float* Kg = g_k + (size_t)(b * KVH + g) * Ss * HD;
    const float* Vg = g_v + (size_t)(b * KVH + g) * Ss * HD;

    __shared__ float Qs[64][64];   // [h][q]
    __shared__ float KP[64][64];   // Ks[h][k] during scores, Ps[q][k] during PV
    __shared__ float Vs[64][64];   // [k][h]

    int tid = threadIdx.x;
    int tq = (tid >> 4) * 4;       // 4 query rows
    int tk = (tid & 15) * 4;       // 4 key cols (== 4 out dims in PV)
    int lrow = tid >> 2;           // loader row 0..63
    int lhb  = (tid & 3) * 16;     // loader col base

    // load Q transposed into Qs[h][q]
#pragma unroll
    for (int i = 0; i < 16; i += 4) {
        float4 val = *(const float4*)(Qg + lrow * HD + lhb + i);
        Qs[lhb + i + 0][lrow] = val.x; Qs[lhb + i + 1][lrow] = val.y;
        Qs[lhb + i + 2][lrow] = val.z; Qs[lhb + i + 3][lrow] = val.w;
    }

    float mr[4], lsum[4], acc[4][4];
#pragma unroll
    for (int i = 0; i < 4; i++) {
        mr[i] = -1e30f; lsum[i] = 0.f;
#pragma unroll
        for (int j = 0; j < 4; j++) acc[i][j] = 0.f;
    }

    for (int kt = 0; kt <= qb; kt++) {
        __syncthreads();   // previous PV done with KP/Vs
        {
            const float* Kt = Kg + (size_t)(kt * 64 + lrow) * HD + lhb;
            const float* Vt = Vg + (size_t)(kt * 64 + lrow) * HD + lhb;
#pragma unroll
            for (int i = 0; i < 16; i += 4) {
                float4 kv = *(const float4*)(Kt + i);
                KP[lhb + i + 0][lrow] = kv.x; KP[lhb + i + 1][lrow] = kv.y;
                KP[lhb + i + 2][lrow] = kv.z; KP[lhb + i + 3][lrow] = kv.w;
                *(float4*)&Vs[lrow][lhb + i] = *(const float4*)(Vt + i);
            }
        }
        __syncthreads();

        // scores: sc[i][j] = Q[tq+i] . K[tk+j]
        float sc[4][4];
#pragma unroll
        for (int i = 0; i < 4; i++)
#pragma unroll
            for (int j = 0; j < 4; j++) sc[i][j] = 0.f;
        for (int h = 0; h < HD; h++) {
            float4 qa = *(const float4*)&Qs[h][tq];
            float4 kb = *(const float4*)&KP[h][tk];
            float aq[4] = {qa.x, qa.y, qa.z, qa.w};
            float bk[4] = {kb.x, kb.y, kb.z, kb.w};
#pragma unroll
            for (int i = 0; i < 4; i++)
#pragma unroll
                for (int j = 0; j < 4; j++)
                    sc[i][j] = fmaf(aq[i], bk[j], sc[i][j]);
        }
        __syncthreads();   // everyone done reading KP as Ks

        // scale -> softcap (50*tanh(s/50)) -> causal mask
#pragma unroll
        for (int i = 0; i < 4; i++) {
#pragma unroll
            for (int j = 0; j < 4; j++) {
                float z = sc[i][j] * (0.125f * 0.02f);   // (1/sqrt(64)) / 50
                float t = 1.f - 2.f / (__expf(2.f * z) + 1.f);   // tanh(z)
                float sv = 50.f * t;
                if (kt == qb && (tk + j) > (tq + i)) sv = -1e30f;
                sc[i][j] = sv;
            }
        }

        // online softmax per row; 16 threads (one half-warp) share a row group
#pragma unroll
        for (int i = 0; i < 4; i++) {
            float rm = fmaxf(fmaxf(sc[i][0], sc[i][1]), fmaxf(sc[i][2], sc[i][3]));
#pragma unroll
            for (int o = 8; o >= 1; o >>= 1)
                rm = fmaxf(rm, __shfl_xor_sync(0xffffffffu, rm, o));
            float mnew = fmaxf(mr[i], rm);
            float alpha = __expf(mr[i] - mnew);
            mr[i] = mnew;
            float p0 = __expf(sc[i][0] - mnew);
            float p1 = __expf(sc[i][1] - mnew);
            float p2 = __expf(sc[i][2] - mnew);
            float p3 = __expf(sc[i][3] - mnew);
            float rs = (p0 + p1) + (p2 + p3);
#pragma unroll
            for (int o = 8; o >= 1; o >>= 1)
                rs += __shfl_xor_sync(0xffffffffu, rs, o);
            lsum[i] = lsum[i] * alpha + rs;
#pragma unroll
            for (int j = 0; j < 4; j++) acc[i][j] *= alpha;
            *(float4*)&KP[tq + i][tk] = make_float4(p0, p1, p2, p3);  // Ps
        }
        __syncthreads();   // Ps visible

        // PV: acc[i][j] += sum_k Ps[tq+i][k] * Vs[k][tk+j]
        for (int k4 = 0; k4 < 64; k4 += 4) {
            float pa[4][4], vb[4][4];
#pragma unroll
            for (int i = 0; i < 4; i++) {
                float4 pr = *(const float4*)&KP[tq + i][k4];
                pa[i][0] = pr.x; pa[i][1] = pr.y; pa[i][2] = pr.z; pa[i][3] = pr.w;
            }
#pragma unroll
            for (int kk = 0; kk < 4; kk++) {
                float4 vr = *(const float4*)&Vs[k4 + kk][tk];
                vb[kk][0] = vr.x; vb[kk][1] = vr.y; vb[kk][2] = vr.z; vb[kk][3] = vr.w;
            }
#pragma unroll
            for (int i = 0; i < 4; i++)
#pragma unroll
                for (int kk = 0; kk < 4; kk++)
#pragma unroll
                    for (int j = 0; j < 4; j++)
                        acc[i][j] = fmaf(pa[i][kk], vb[kk][j], acc[i][j]);
        }
    }

    // epilogue: normalize and write attn in [b][s][gp*64+h] layout
    int colbase = gp * 64 + tk;
#pragma unroll
    for (int i = 0; i < 4; i++) {
        float inv = 1.f / lsum[i];
        int srow = qb * 64 + tq + i;
        float4 o = make_float4(acc[i][0] * inv, acc[i][1] * inv,
                               acc[i][2] * inv, acc[i][3] * inv);
        *(float4*)&g_attn[((size_t)(b * Ss + srow)) * NQ + colbase] = o;
    }
}

// ---------------- launch ---------------------------------------------------
extern "C" void kernel_launch(void* const* d_in, const int* in_sizes, int n_in,
                              void* d_out, int out_size)
{
    const float* x  = (const float*)d_in[0];
    const float* wq = (const float*)d_in[1];
    const float* wk = (const float*)d_in[2];
    const float* wv = (const float*)d_in[3];
    const float* wo = (const float*)d_in[4];
    const float* qn = (const float*)d_in[5];
    const float* kn = (const float*)d_in[6];
    const int* pos  = (const int*)d_in[7];
    float* out = (float*)d_out;

    float* qkv;
    cudaGetSymbolAddress((void**)&qkv, g_qkv);
    float* attn;
    cudaGetSymbolAddress((void**)&attn, g_attn);

    // 1) fused QKV projection: [4096,2048] @ [3072,2048]^T -> g_qkv
    //    16 q-blocks of 128 cols, 4 k-blocks, 4 v-blocks
    gemm_nt<<<dim3(24, 32), 256>>>(x, wq, wk, wv, 16, 4, qkv, Dd, NTOT);

    // 2) rmsnorm + rope + scatter
    norm_rope<<<Mtot, 256>>>(qn, kn, pos);

    // 3) flash attention, 64 heads x 32 query tiles
    flash_attn<<<dim3(32, 64), 256>>>();

    // 4) output projection: [4096,2048] @ wo[2048,2048]^T -> out
    gemm_nt<<<dim3(16, 32), 256>>>(attn, wo, wo, wo, 16, 0, out, NQ, Dd);
}

// round 3
// speedup vs baseline: 1.5548x; 1.5548x over previous
#include <cuda_runtime.h>
#include <cuda_bf16.h>
#include <cstdint>

#define Bb 2
#define Ss 2048
#define Dd 2048
#define KVH 8
#define QPG 4
#define HD 64
#define Mtot (Bb*Ss)            // 4096
#define NQ (KVH*QPG*HD)         // 2048
#define NKV (KVH*HD)            // 512
#define NTOT (NQ + 2*NKV)       // 3072

// ---------------- scratch (module-load static, no runtime allocs) ----------
__device__ float g_qkv[(size_t)Mtot * NTOT];
__device__ float g_q[(size_t)Bb*KVH*QPG*Ss*HD];              // [b][gp][s][h]
__device__ float g_k[(size_t)Bb*KVH*Ss*HD];                  // [b][g][s][h]
__device__ float g_v[(size_t)Bb*KVH*Ss*HD];
__device__ float g_attn[(size_t)Mtot * NQ];                  // [b][s][gp*64+h]

// bf16 hi/lo split copies for tensor-core GEMMs
__device__ unsigned short g_xh[(size_t)Mtot*Dd], g_xl[(size_t)Mtot*Dd];
__device__ unsigned short g_wh[(size_t)NTOT*Dd], g_wl[(size_t)NTOT*Dd];
__device__ unsigned short g_oh[(size_t)Dd*NQ],  g_ol[(size_t)Dd*NQ];
__device__ unsigned short g_ah[(size_t)Mtot*NQ], g_al[(size_t)Mtot*NQ];

// ---------------- helpers ---------------------------------------------------
__device__ __forceinline__ uint32_t s2u(const void* p){
    uint32_t a;
    asm("{ .reg .u64 t; cvta.to.shared.u64 t, %1; cvt.u32.u64 %0, t; }":"=r"(a):"l"(p));
    return a;
}
__device__ __forceinline__ void cp16(uint32_t d, const void* g){
    asm volatile("cp.async.cg.shared.global [%0], [%1], 16;" :: "r"(d), "l"(g));
}
__device__ __forceinline__ void mma16816(float* c, const uint32_t* a, const uint32_t* b){
    asm volatile("mma.sync.aligned.m16n8k16.row.col.f32.bf16.bf16.f32 "
        "{%0,%1,%2,%3}, {%4,%5,%6,%7}, {%8,%9}, {%0,%1,%2,%3};"
        : "+f"(c[0]), "+f"(c[1]), "+f"(c[2]), "+f"(c[3])
        : "r"(a[0]), "r"(a[1]), "r"(a[2]), "r"(a[3]), "r"(b[0]), "r"(b[1]));
}

// ---------------- fp32 -> bf16 hi/lo split ---------------------------------
__global__ __launch_bounds__(256) void split_hl(const float4* __restrict__ s,
        uint2* __restrict__ hi, uint2* __restrict__ lo, int n4)
{
    int i = blockIdx.x*blockDim.x + threadIdx.x;
    if (i >= n4) return;
    float4 v = s[i];
    float f[4] = {v.x, v.y, v.z, v.w};
    unsigned short h[4], l[4];
#pragma unroll
    for (int j = 0; j < 4; j++){
        __nv_bfloat16 hb = __float2bfloat16(f[j]);
        float r = f[j] - __bfloat162float(hb);
        __nv_bfloat16 lb = __float2bfloat16(r);
        h[j] = *(unsigned short*)&hb;
        l[j] = *(unsigned short*)&lb;
    }
    hi[i] = make_uint2((uint32_t)h[0] | ((uint32_t)h[1]<<16),
                       (uint32_t)h[2] | ((uint32_t)h[3]<<16));
    lo[i] = make_uint2((uint32_t)l[0] | ((uint32_t)l[1]<<16),
                       (uint32_t)l[2] | ((uint32_t)l[3]<<16));
}

// ---------------- HMMA GEMM: C = A @ B^T (bf16 hi/lo split, fp32 acc) ------
// Tiles 128x128x32, 2-stage cp.async pipeline, 8 warps (2x4), 64x32 per warp.
// smem per stage: 4 tiles (Ah,Al,Bh,Bl), each 128 rows x 40 bf16 (padded).
#define T_ELEMS (128*40)          // 5120 elems per tile
#define STG_ELEMS (4*T_ELEMS)     // 20480
#define GEMM_SMEM (2*STG_ELEMS*2) // 81920 bytes

__global__ __launch_bounds__(256, 1) void gemm_mma(
    const unsigned short* __restrict__ Ah, const unsigned short* __restrict__ Al,
    const unsigned short* __restrict__ Bh, const unsigned short* __restrict__ Bl,
    float* __restrict__ C, int Kd, int ldc)
{
    extern __shared__ unsigned short sm[];
    const int tid = threadIdx.x, lane = tid & 31, wid = tid >> 5;
    const int wm = wid >> 2, wn = wid & 3;      // 2 x 4 warp grid
    const int g = lane >> 2, t = lane & 3;
    const int Mb = blockIdx.y * 128, Nb = blockIdx.x * 128;
    const int NC = Kd >> 5;                      // K chunks of 32

    float acc[4][4][4];
#pragma unroll
    for (int mt = 0; mt < 4; mt++)
#pragma unroll
        for (int nt = 0; nt < 4; nt++)
#pragma unroll
            for (int r = 0; r < 4; r++) acc[mt][nt][r] = 0.f;

    const int lrow = tid >> 1;           // 0..127
    const int cb   = (tid & 1) * 2;      // chunk base (16B chunks of 8 bf16)

    auto prefetch = [&](int c){
        unsigned short* s = sm + (c & 1) * STG_ELEMS;
        const int k0 = c << 5;
        const size_t ga = (size_t)(Mb + lrow) * Kd + k0;
        const size_t gb = (size_t)(Nb + lrow) * Kd + k0;
#pragma unroll
        for (int ch = cb; ch < cb + 2; ch++){
            uint32_t so = lrow * 40 + ch * 8;
            cp16(s2u(s + so),              Ah + ga + ch * 8);
            cp16(s2u(s + T_ELEMS   + so),  Al + ga + ch * 8);
            cp16(s2u(s + 2*T_ELEMS + so),  Bh + gb + ch * 8);
            cp16(s2u(s + 3*T_ELEMS + so),  Bl + gb + ch * 8);
        }
        asm volatile("cp.async.commit_group;" ::: "memory");
    };

    prefetch(0);
    for (int c = 0; c < NC; c++) {
        if (c + 1 < NC) {
            prefetch(c + 1);
            asm volatile("cp.async.wait_group 1;" ::: "memory");
        } else {
            asm volatile("cp.async.wait_group 0;" ::: "memory");
        }
        __syncthreads();

        const unsigned short* s = sm + (c & 1) * STG_ELEMS;
#pragma unroll
        for (int kk = 0; kk < 2; kk++) {
            const int kb = kk * 16 + t * 2;
            uint32_t ah[4][4], al[4][4], bh[4][2], bl[4][2];
#pragma unroll
            for (int mt = 0; mt < 4; mt++) {
                const unsigned short* p = s + (wm*64 + mt*16 + g) * 40 + kb;
                ah[mt][0] = *(const uint32_t*)(p);
                ah[mt][1] = *(const uint32_t*)(p + 8*40);
                ah[mt][2] = *(const uint32_t*)(p + 8);
                ah[mt][3] = *(const uint32_t*)(p + 8*40 + 8);
                const unsigned short* q = p + T_ELEMS;
                al[mt][0] = *(const uint32_t*)(q);
                al[mt][1] = *(const uint32_t*)(q + 8*40);
                al[mt][2] = *(const uint32_t*)(q + 8);
                al[mt][3] = *(const uint32_t*)(q + 8*40 + 8);
            }
#pragma unroll
            for (int nt = 0; nt < 4; nt++) {
                const unsigned short* p = s + 2*T_ELEMS + (wn*32 + nt*8 + g) * 40 + kb;
                bh[nt][0] = *(const uint32_t*)(p);
                bh[nt][1] = *(const uint32_t*)(p + 8);
                const unsigned short* q = p + T_ELEMS;
                bl[nt][0] = *(const uint32_t*)(q);
                bl[nt][1] = *(const uint32_t*)(q + 8);
            }
#pragma unroll
            for (int mt = 0; mt < 4; mt++)
#pragma unroll
                for (int nt = 0; nt < 4; nt++) {
                    mma16816(acc[mt][nt], ah[mt], bh[nt]);
                    mma16816(acc[mt][nt], ah[mt], bl[nt]);
                    mma16816(acc[mt][nt], al[mt], bh[nt]);
                }
        }
        __syncthreads();
    }

#pragma unroll
    for (int mt = 0; mt < 4; mt++) {
        int row = Mb + wm*64 + mt*16 + g;
#pragma unroll
        for (int nt = 0; nt < 4; nt++) {
            int col = Nb + wn*32 + nt*8 + t*2;
            *(float2*)&C[(size_t)row * ldc + col] =
                make_float2(acc[mt][nt][0], acc[mt][nt][1]);
            *(float2*)&C[(size_t)(row + 8) * ldc + col] =
                make_float2(acc[mt][nt][2], acc[mt][nt][3]);
        }
    }
}

// ---------------- RMSNorm + partial RoPE + scatter -------------------------
__global__ __launch_bounds__(256) void norm_rope(
    const float* __restrict__ qn, const float* __restrict__ kn,
    const int* __restrict__ pos_ids)
{
    int m = blockIdx.x;
    int b = m / Ss, s = m % Ss;
    int warp = threadIdx.x >> 5, lane = threadIdx.x & 31;
    float pos = (float)pos_ids[s];

    for (int iv = warp; iv < 48; iv += 8) {
        const float* src = g_qkv + (size_t)m * NTOT + iv * 64;
        float x1 = src[lane], x2 = src[lane + 32];
        if (iv < 40) {
            float ssum = x1 * x1 + x2 * x2;
#pragma unroll
            for (int o = 16; o >= 1; o >>= 1)
                ssum += __shfl_xor_sync(0xffffffffu, ssum, o);
            float inv = rsqrtf(ssum * (1.f / 64.f) + 1e-5f);
            const float* w = (iv < 32) ? qn : kn;
            x1 = x1 * inv * w[lane];
            x2 = x2 * inv * w[lane + 32];
            float invf = (lane < 16) ? exp2f(-0.625f * (float)lane) : 0.f;
            float f = pos * invf;
            float sn = sinf(f), cs = cosf(f);
            float o1 = x1 * cs - x2 * sn;
            float o2 = x2 * cs + x1 * sn;
            x1 = o1; x2 = o2;
        }
        float* dst;
        if (iv < 32)      dst = g_q + ((size_t)(b * 32 + iv) * Ss + s) * HD;
        else if (iv < 40) dst = g_k + ((size_t)(b * KVH + (iv - 32)) * Ss + s) * HD;
        else              dst = g_v + ((size_t)(b * KVH + (iv - 40)) * Ss + s) * HD;
        dst[lane] = x1;
        dst[lane + 32] = x2;
    }
}

// ---------------- Flash attention (SIMT) -----------------------------------
__global__ __launch_bounds__(256) void flash_attn()
{
    int head = blockIdx.y;
    int qb = gridDim.x - 1 - blockIdx.x;
    int b = head >> 5, gp = head & 31, g = gp >> 2;

    const float* Qg = g_q + ((size_t)head * Ss + qb * 64) * HD;
    const float* Kg = g_k + (size_t)(b * KVH + g) * Ss * HD;
    const float* Vg = g_v + (size_t)(b * KVH + g) * Ss * HD;

    __shared__ float Qs[64][64];
    __shared__ float KP[64][64];
    __shared__ float Vs[64][64];

    int tid = threadIdx.x;
    int tq = (tid >> 4) * 4;
    int tk = (tid & 15) * 4;
    int lrow = tid >> 2;
    int lhb  = (tid & 3) * 16;

#pragma unroll
    for (int i = 0; i < 16; i += 4) {
        float4 val = *(const float4*)(Qg + lrow * HD + lhb + i);
        Qs[lhb + i + 0][lrow] = val.x; Qs[lhb + i + 1][lrow] = val.y;
        Qs[lhb + i + 2][lrow] = val.z; Qs[lhb + i + 3][lrow] = val.w;
    }

    float mr[4], lsum[4], acc[4][4];
#pragma unroll
    for (int i = 0; i < 4; i++) {
        mr[i] = -1e30f; lsum[i] = 0.f;
#pragma unroll
        for (int j = 0; j < 4; j++) acc[i][j] = 0.f;
    }

    for (int kt = 0; kt <= qb; kt++) {
        __syncthreads();
        {
            const float* Kt = Kg + (size_t)(kt * 64 + lrow) * HD + lhb;
            const float* Vt = Vg + (size_t)(kt * 64 + lrow) * HD + lhb;
#pragma unroll
            for (int i = 0; i < 16; i += 4) {
                float4 kv = *(const float4*)(Kt + i);
                KP[lhb + i + 0][lrow] = kv.x; KP[lhb + i + 1][lrow] = kv.y;
                KP[lhb + i + 2][lrow] = kv.z; KP[lhb + i + 3][lrow] = kv.w;
                *(float4*)&Vs[lrow][lhb + i] = *(const float4*)(Vt + i);
            }
        }
        __syncthreads();

        float sc[4][4];
#pragma unroll
        for (int i = 0; i < 4; i++)
#pragma unroll
            for (int j = 0; j < 4; j++) sc[i][j] = 0.f;
        for (int h = 0; h < HD; h++) {
            float4 qa = *(const float4*)&Qs[h][tq];
            float4 kb = *(const float4*)&KP[h][tk];
            float aq[4] = {qa.x, qa.y, qa.z, qa.w};
            float bk[4] = {kb.x, kb.y, kb.z, kb.w};
#pragma unroll
            for (int i = 0; i < 4; i++)
#pragma unroll
                for (int j = 0; j < 4; j++)
                    sc[i][j] = fmaf(aq[i], bk[j], sc[i][j]);
        }
        __syncthreads();

#pragma unroll
        for (int i = 0; i < 4; i++) {
#pragma unroll
            for (int j = 0; j < 4; j++) {
                float z = sc[i][j] * (0.125f * 0.02f);
                float t = 1.f - 2.f / (__expf(2.f * z) + 1.f);
                float sv = 50.f * t;
                if (kt == qb && (tk + j) > (tq + i)) sv = -1e30f;
                sc[i][j] = sv;
            }
        }

#pragma unroll
        for (int i = 0; i < 4; i++) {
            float rm = fmaxf(fmaxf(sc[i][0], sc[i][1]), fmaxf(sc[i][2], sc[i][3]));
#pragma unroll
            for (int o = 8; o >= 1; o >>= 1)
                rm = fmaxf(rm, __shfl_xor_sync(0xffffffffu, rm, o));
            float mnew = fmaxf(mr[i], rm);
            float alpha = __expf(mr[i] - mnew);
            mr[i] = mnew;
            float p0 = __expf(sc[i][0] - mnew);
            float p1 = __expf(sc[i][1] - mnew);
            float p2 = __expf(sc[i][2] - mnew);
            float p3 = __expf(sc[i][3] - mnew);
            float rs = (p0 + p1) + (p2 + p3);
#pragma unroll
            for (int o = 8; o >= 1; o >>= 1)
                rs += __shfl_xor_sync(0xffffffffu, rs, o);
            lsum[i] = lsum[i] * alpha + rs;
#pragma unroll
            for (int j = 0; j < 4; j++) acc[i][j] *= alpha;
            *(float4*)&KP[tq + i][tk] = make_float4(p0, p1, p2, p3);
        }
        __syncthreads();

        for (int k4 = 0; k4 < 64; k4 += 4) {
            float pa[4][4], vb[4][4];
#pragma unroll
            for (int i = 0; i < 4; i++) {
                float4 pr = *(const float4*)&KP[tq + i][k4];
                pa[i][0] = pr.x; pa[i][1] = pr.y; pa[i][2] = pr.z; pa[i][3] = pr.w;
            }
#pragma unroll
            for (int kk = 0; kk < 4; kk++) {
                float4 vr = *(const float4*)&Vs[k4 + kk][tk];
                vb[kk][0] = vr.x; vb[kk][1] = vr.y; vb[kk][2] = vr.z; vb[kk][3] = vr.w;
            }
#pragma unroll
            for (int i = 0; i < 4; i++)
#pragma unroll
                for (int kk = 0; kk < 4; kk++)
#pragma unroll
                    for (int j = 0; j < 4; j++)
                        acc[i][j] = fmaf(pa[i][kk], vb[kk][j], acc[i][j]);
        }
    }

    int colbase = gp * 64 + tk;
#pragma unroll
    for (int i = 0; i < 4; i++) {
        float inv = 1.f / lsum[i];
        int srow = qb * 64 + tq + i;
        float4 o = make_float4(acc[i][0] * inv, acc[i][1] * inv,
                               acc[i][2] * inv, acc[i][3] * inv);
        *(float4*)&g_attn[((size_t)(b * Ss + srow)) * NQ + colbase] = o;
    }
}

// ---------------- launch ---------------------------------------------------
extern "C" void kernel_launch(void* const* d_in, const int* in_sizes, int n_in,
                              void* d_out, int out_size)
{
    const float* x  = (const float*)d_in[0];
    const float* wq = (const float*)d_in[1];
    const float* wk = (const float*)d_in[2];
    const float* wv = (const float*)d_in[3];
    const float* wo = (const float*)d_in[4];
    const float* qn = (const float*)d_in[5];
    const float* kn = (const float*)d_in[6];
    const int* pos  = (const int*)d_in[7];
    float* out = (float*)d_out;

    float *qkv, *attn;
    cudaGetSymbolAddress((void**)&qkv, g_qkv);
    cudaGetSymbolAddress((void**)&attn, g_attn);
    unsigned short *xh, *xl, *wh, *wl, *oh, *ol, *ah, *al;
    cudaGetSymbolAddress((void**)&xh, g_xh);  cudaGetSymbolAddress((void**)&xl, g_xl);
    cudaGetSymbolAddress((void**)&wh, g_wh);  cudaGetSymbolAddress((void**)&wl, g_wl);
    cudaGetSymbolAddress((void**)&oh, g_oh);  cudaGetSymbolAddress((void**)&ol, g_ol);
    cudaGetSymbolAddress((void**)&ah, g_ah);  cudaGetSymbolAddress((void**)&al, g_al);

    cudaFuncSetAttribute(gemm_mma, cudaFuncAttributeMaxDynamicSharedMemorySize, GEMM_SMEM);

    // 0) split fp32 -> bf16 hi/lo
    split_hl<<<8192, 256>>>((const float4*)x,  (uint2*)xh, (uint2*)xl, 2097152);
    split_hl<<<4096, 256>>>((const float4*)wq, (uint2*)wh, (uint2*)wl, 1048576);
    split_hl<<<1024, 256>>>((const float4*)wk, (uint2*)(wh + 4194304), (uint2*)(wl + 4194304), 262144);
    split_hl<<<1024, 256>>>((const float4*)wv, (uint2*)(wh + 5242880), (uint2*)(wl + 5242880), 262144);
    split_hl<<<4096, 256>>>((const float4*)wo, (uint2*)oh, (uint2*)ol, 1048576);

    // 1) QKV projection (HMMA): [4096,2048] @ [3072,2048]^T -> g_qkv
    gemm_mma<<<dim3(24, 32), 256, GEMM_SMEM>>>(xh, xl, wh, wl, qkv, Dd, NTOT);

    // 2) rmsnorm + rope + scatter
    norm_rope<<<Mtot, 256>>>(qn, kn, pos);

    // 3) flash attention
    flash_attn<<<dim3(32, 64), 256>>>();

    // 4) split attn, then output projection (HMMA)
    split_hl<<<8192, 256>>>((const float4*)attn, (uint2*)ah, (uint2*)al, 2097152);
    gemm_mma<<<dim3(16, 32), 256, GEMM_SMEM>>>(ah, al, oh, ol, out, Dd, Dd);
}

// round 4
// speedup vs baseline: 2.5483x; 1.6389x over previous
#include <cuda_runtime.h>
#include <cuda_bf16.h>
#include <cstdint>

#define Bb 2
#define Ss 2048
#define Dd 2048
#define KVH 8
#define QPG 4
#define HD 64
#define Mtot (Bb*Ss)            // 4096
#define NQ (KVH*QPG*HD)         // 2048
#define NKV (KVH*HD)            // 512
#define NTOT (NQ + 2*NKV)       // 3072

// ---------------- scratch (module-load static, no runtime allocs) ----------
__device__ float g_qkv[(size_t)Mtot * NTOT];

// bf16 hi/lo split tensors
__device__ unsigned short g_xh[(size_t)Mtot*Dd], g_xl[(size_t)Mtot*Dd];
__device__ unsigned short g_wh[(size_t)NTOT*Dd], g_wl[(size_t)NTOT*Dd];
__device__ unsigned short g_oh[(size_t)Dd*NQ],  g_ol[(size_t)Dd*NQ];
__device__ unsigned short g_ah[(size_t)Mtot*NQ], g_al[(size_t)Mtot*NQ];
// attention operands (hi/lo):
__device__ unsigned short g_qh[(size_t)64*Ss*HD], g_ql[(size_t)64*Ss*HD];   // [head][s][h]
__device__ unsigned short g_kh[(size_t)16*Ss*HD], g_kl[(size_t)16*Ss*HD];   // [bg][s][h]
__device__ unsigned short g_vth[(size_t)16*HD*Ss], g_vtl[(size_t)16*HD*Ss]; // [bg][h][s]

// ---------------- helpers ---------------------------------------------------
__device__ __forceinline__ uint32_t s2u(const void* p){
    uint32_t a;
    asm("{ .reg .u64 t; cvta.to.shared.u64 t, %1; cvt.u32.u64 %0, t; }":"=r"(a):"l"(p));
    return a;
}
__device__ __forceinline__ void cp16(uint32_t d, const void* g){
    asm volatile("cp.async.cg.shared.global [%0], [%1], 16;" :: "r"(d), "l"(g));
}
__device__ __forceinline__ void mma16816(float* c, const uint32_t* a, const uint32_t* b){
    asm volatile("mma.sync.aligned.m16n8k16.row.col.f32.bf16.bf16.f32 "
        "{%0,%1,%2,%3}, {%4,%5,%6,%7}, {%8,%9}, {%0,%1,%2,%3};"
        : "+f"(c[0]), "+f"(c[1]), "+f"(c[2]), "+f"(c[3])
        : "r"(a[0]), "r"(a[1]), "r"(a[2]), "r"(a[3]), "r"(b[0]), "r"(b[1]));
}
__device__ __forceinline__ void splitf(float x, unsigned short& h, unsigned short& l){
    __nv_bfloat16 hb = __float2bfloat16(x);
    float r = x - __bfloat162float(hb);
    __nv_bfloat16 lb = __float2bfloat16(r);
    h = *(unsigned short*)&hb; l = *(unsigned short*)&lb;
}
// pack (lo,hi) fp32 pair into bf16x2 hi-part and residual lo-part
__device__ __forceinline__ void packhl(float lo, float hi, uint32_t& ph, uint32_t& pl){
    asm("cvt.rn.bf16x2.f32 %0, %1, %2;" : "=r"(ph) : "f"(hi), "f"(lo));
    float flo = __uint_as_float(ph << 16);
    float fhi = __uint_as_float(ph & 0xFFFF0000u);
    asm("cvt.rn.bf16x2.f32 %0, %1, %2;" : "=r"(pl) : "f"(hi - fhi), "f"(lo - flo));
}

// ---------------- fp32 -> bf16 hi/lo split ---------------------------------
__global__ __launch_bounds__(256) void split_hl(const float4* __restrict__ s,
        uint2* __restrict__ hi, uint2* __restrict__ lo, int n4)
{
    int i = blockIdx.x*blockDim.x + threadIdx.x;
    if (i >= n4) return;
    float4 v = s[i];
    float f[4] = {v.x, v.y, v.z, v.w};
    unsigned short h[4], l[4];
#pragma unroll
    for (int j = 0; j < 4; j++) splitf(f[j], h[j], l[j]);
    hi[i] = make_uint2((uint32_t)h[0] | ((uint32_t)h[1]<<16),
                       (uint32_t)h[2] | ((uint32_t)h[3]<<16));
    lo[i] = make_uint2((uint32_t)l[0] | ((uint32_t)l[1]<<16),
                       (uint32_t)l[2] | ((uint32_t)l[3]<<16));
}

// ---------------- HMMA GEMM (unchanged from R3) ----------------------------
#define T_ELEMS (128*40)
#define STG_ELEMS (4*T_ELEMS)
#define GEMM_SMEM (2*STG_ELEMS*2)

__global__ __launch_bounds__(256, 1) void gemm_mma(
    const unsigned short* __restrict__ Ah, const unsigned short* __restrict__ Al,
    const unsigned short* __restrict__ Bh, const unsigned short* __restrict__ Bl,
    float* __restrict__ C, int Kd, int ldc)
{
    extern __shared__ unsigned short sm[];
    const int tid = threadIdx.x, lane = tid & 31, wid = tid >> 5;
    const int wm = wid >> 2, wn = wid & 3;
    const int g = lane >> 2, t = lane & 3;
    const int Mb = blockIdx.y * 128, Nb = blockIdx.x * 128;
    const int NC = Kd >> 5;

    float acc[4][4][4];
#pragma unroll
    for (int mt = 0; mt < 4; mt++)
#pragma unroll
        for (int nt = 0; nt < 4; nt++)
#pragma unroll
            for (int r = 0; r < 4; r++) acc[mt][nt][r] = 0.f;

    const int lrow = tid >> 1;
    const int cb   = (tid & 1) * 2;

    auto prefetch = [&](int c){
        unsigned short* s = sm + (c & 1) * STG_ELEMS;
        const int k0 = c << 5;
        const size_t ga = (size_t)(Mb + lrow) * Kd + k0;
        const size_t gb = (size_t)(Nb + lrow) * Kd + k0;
#pragma unroll
        for (int ch = cb; ch < cb + 2; ch++){
            uint32_t so = lrow * 40 + ch * 8;
            cp16(s2u(s + so),              Ah + ga + ch * 8);
            cp16(s2u(s + T_ELEMS   + so),  Al + ga + ch * 8);
            cp16(s2u(s + 2*T_ELEMS + so),  Bh + gb + ch * 8);
            cp16(s2u(s + 3*T_ELEMS + so),  Bl + gb + ch * 8);
        }
        asm volatile("cp.async.commit_group;" ::: "memory");
    };

    prefetch(0);
    for (int c = 0; c < NC; c++) {
        if (c + 1 < NC) {
            prefetch(c + 1);
            asm volatile("cp.async.wait_group 1;" ::: "memory");
        } else {
            asm volatile("cp.async.wait_group 0;" ::: "memory");
        }
        __syncthreads();

        const unsigned short* s = sm + (c & 1) * STG_ELEMS;
#pragma unroll
        for (int kk = 0; kk < 2; kk++) {
            const int kb = kk * 16 + t * 2;
            uint32_t ah[4][4], al[4][4], bh[4][2], bl[4][2];
#pragma unroll
            for (int mt = 0; mt < 4; mt++) {
                const unsigned short* p = s + (wm*64 + mt*16 + g) * 40 + kb;
                ah[mt][0] = *(const uint32_t*)(p);
                ah[mt][1] = *(const uint32_t*)(p + 8*40);
                ah[mt][2] = *(const uint32_t*)(p + 8);
                ah[mt][3] = *(const uint32_t*)(p + 8*40 + 8);
                const unsigned short* q = p + T_ELEMS;
                al[mt][0] = *(const uint32_t*)(q);
                al[mt][1] = *(const uint32_t*)(q + 8*40);
                al[mt][2] = *(const uint32_t*)(q + 8);
                al[mt][3] = *(const uint32_t*)(q + 8*40 + 8);
            }
#pragma unroll
            for (int nt = 0; nt < 4; nt++) {
                const unsigned short* p = s + 2*T_ELEMS + (wn*32 + nt*8 + g) * 40 + kb;
                bh[nt][0] = *(const uint32_t*)(p);
                bh[nt][1] = *(const uint32_t*)(p + 8);
                const unsigned short* q = p + T_ELEMS;
                bl[nt][0] = *(const uint32_t*)(q);
                bl[nt][1] = *(const uint32_t*)(q + 8);
            }
#pragma unroll
            for (int mt = 0; mt < 4; mt++)
#pragma unroll
                for (int nt = 0; nt < 4; nt++) {
                    mma16816(acc[mt][nt], ah[mt], bh[nt]);
                    mma16816(acc[mt][nt], ah[mt], bl[nt]);
                    mma16816(acc[mt][nt], al[mt], bh[nt]);
                }
        }
        __syncthreads();
    }

#pragma unroll
    for (int mt = 0; mt < 4; mt++) {
        int row = Mb + wm*64 + mt*16 + g;
#pragma unroll
        for (int nt = 0; nt < 4; nt++) {
            int col = Nb + wn*32 + nt*8 + t*2;
            *(float2*)&C[(size_t)row * ldc + col] =
                make_float2(acc[mt][nt][0], acc[mt][nt][1]);
            *(float2*)&C[(size_t)(row + 8) * ldc + col] =
                make_float2(acc[mt][nt][2], acc[mt][nt][3]);
        }
    }
}

// ---------------- RMSNorm + partial RoPE -> bf16 hi/lo scatter -------------
__global__ __launch_bounds__(256) void norm_rope(
    const float* __restrict__ qn, const float* __restrict__ kn,
    const int* __restrict__ pos_ids)
{
    int m = blockIdx.x;
    int b = m / Ss, s = m % Ss;
    int warp = threadIdx.x >> 5, lane = threadIdx.x & 31;
    float pos = (float)pos_ids[s];

    for (int iv = warp; iv < 48; iv += 8) {
        const float* src = g_qkv + (size_t)m * NTOT + iv * 64;
        float x1 = src[lane], x2 = src[lane + 32];
        if (iv < 40) {
            float ssum = x1 * x1 + x2 * x2;
#pragma unroll
            for (int o = 16; o >= 1; o >>= 1)
                ssum += __shfl_xor_sync(0xffffffffu, ssum, o);
            float inv = rsqrtf(ssum * (1.f / 64.f) + 1e-5f);
            const float* w = (iv < 32) ? qn : kn;
            x1 = x1 * inv * w[lane];
            x2 = x2 * inv * w[lane + 32];
            float invf = (lane < 16) ? exp2f(-0.625f * (float)lane) : 0.f;
            float f = pos * invf;
            float sn = sinf(f), cs = cosf(f);
            float o1 = x1 * cs - x2 * sn;
            float o2 = x2 * cs + x1 * sn;
            x1 = o1; x2 = o2;
        }
        unsigned short h1, l1, h2, l2;
        splitf(x1, h1, l1); splitf(x2, h2, l2);
        if (iv < 32) {
            size_t base = ((size_t)(b * 32 + iv) * Ss + s) * HD;
            g_qh[base + lane] = h1;      g_ql[base + lane] = l1;
            g_qh[base + lane + 32] = h2; g_ql[base + lane + 32] = l2;
        } else if (iv < 40) {
            size_t base = ((size_t)(b * KVH + (iv - 32)) * Ss + s) * HD;
            g_kh[base + lane] = h1;      g_kl[base + lane] = l1;
            g_kh[base + lane + 32] = h2; g_kl[base + lane + 32] = l2;
        } else {
            size_t base = (size_t)(b * KVH + (iv - 40)) * HD * Ss;
            g_vth[base + (size_t)lane * Ss + s] = h1;
            g_vtl[base + (size_t)lane * Ss + s] = l1;
            g_vth[base + (size_t)(lane + 32) * Ss + s] = h2;
            g_vtl[base + (size_t)(lane + 32) * Ss + s] = l2;
        }
    }
}

// ---------------- MMA flash attention --------------------------------------
// CTA: one head x 128 q-rows. 8 warps x 16 rows. 64-key tiles, double buffer.
// smem (ushorts): QH[128*72], QL[128*72], 2 stages of {KH,KL,VTH,VTL}[64*72].
#define QT (128*72)               // 9216
#define KT (64*72)                // 4608
#define AST (4*KT)                // stage: 18432
#define ATT_SMEM ((2*QT + 2*AST)*2)   // 110592 bytes

__global__ __launch_bounds__(256, 1) void attn_mma()
{
    extern __shared__ unsigned short sm[];
    const int tid = threadIdx.x, lane = tid & 31, wm = tid >> 5;
    const int g = lane >> 2, t = lane & 3;
    const int head = blockIdx.x;                 // 0..63
    const int qb = 15 - (int)blockIdx.y;         // big tiles first
    const int b = head >> 5, gp = head & 31, kvg = gp >> 2;
    const int rb = qb * 128 + wm * 16;           // warp's first q row (s index)

    const unsigned short* Qh = g_qh + ((size_t)head * Ss + qb * 128) * HD;
    const unsigned short* Ql = g_ql + ((size_t)head * Ss + qb * 128) * HD;
    const unsigned short* Kh = g_kh + (size_t)(b * KVH + kvg) * Ss * HD;
    const unsigned short* Kl = g_kl + (size_t)(b * KVH + kvg) * Ss * HD;
    const unsigned short* Vth = g_vth + (size_t)(b * KVH + kvg) * HD * Ss;
    const unsigned short* Vtl = g_vtl + (size_t)(b * KVH + kvg) * HD * Ss;

    unsigned short* QH = sm;
    unsigned short* QL = sm + QT;

    // ---- prefetch Q (one group) ----
    {
        int row = tid >> 1, cb = (tid & 1) * 4;
#pragma unroll
        for (int c = cb; c < cb + 4; c++) {
            uint32_t so = row * 72 + c * 8;
            cp16(s2u(QH + so), Qh + row * 64 + c * 8);
            cp16(s2u(QL + so), Ql + row * 64 + c * 8);
        }
        asm volatile("cp.async.commit_group;" ::: "memory");
    }

    auto prefetchKV = [&](int kt){
        unsigned short* st = sm + 2*QT + (kt & 1) * AST;
        int row = tid >> 2, cb2 = (tid & 3) * 2;
#pragma unroll
        for (int c = cb2; c < cb2 + 2; c++) {
            uint32_t so = row * 72 + c * 8;
            size_t ofk = (size_t)(kt * 64 + row) * HD + c * 8;
            size_t ofv = (size_t)row * Ss + kt * 64 + c * 8;
            cp16(s2u(st +        so), Kh  + ofk);
            cp16(s2u(st +   KT + so), Kl  + ofk);
            cp16(s2u(st + 2*KT + so), Vth + ofv);
            cp16(s2u(st + 3*KT + so), Vtl + ofv);
        }
        asm volatile("cp.async.commit_group;" ::: "memory");
    };

    prefetchKV(0);

    const int ktmax = 2 * qb + 1;
    float m0 = -1e30f, m1 = -1e30f, l0 = 0.f, l1 = 0.f;
    float oac[8][4];
#pragma unroll
    for (int nt = 0; nt < 8; nt++)
#pragma unroll
        for (int r = 0; r < 4; r++) oac[nt][r] = 0.f;
    uint32_t qfh[4][4], qfl[4][4];

    for (int kt = 0; kt <= ktmax; kt++) {
        if (kt < ktmax) {
            prefetchKV(kt + 1);
            asm volatile("cp.async.wait_group 1;" ::: "memory");
        } else {
            asm volatile("cp.async.wait_group 0;" ::: "memory");
        }
        __syncthreads();

        if (kt == 0) {   // load Q fragments once
#pragma unroll
            for (int ks = 0; ks < 4; ks++) {
                const unsigned short* p = QH + (wm*16 + g) * 72 + ks*16 + t*2;
                qfh[ks][0] = *(const uint32_t*)(p);
                qfh[ks][1] = *(const uint32_t*)(p + 8*72);
                qfh[ks][2] = *(const uint32_t*)(p + 8);
                qfh[ks][3] = *(const uint32_t*)(p + 8*72 + 8);
                const unsigned short* q = QL + (wm*16 + g) * 72 + ks*16 + t*2;
                qfl[ks][0] = *(const uint32_t*)(q);
                qfl[ks][1] = *(const uint32_t*)(q + 8*72);
                qfl[ks][2] = *(const uint32_t*)(q + 8);
                qfl[ks][3] = *(const uint32_t*)(q + 8*72 + 8);
            }
        }

        if (kt * 64 <= rb + 15) {   // tile not fully masked for this warp
            const unsigned short* KH = sm + 2*QT + (kt & 1) * AST;
            const unsigned short* KL = KH + KT;
            const unsigned short* VH = KH + 2*KT;
            const unsigned short* VL = KH + 3*KT;

            // ---- S = Q K^T (3-term) ----
            float sc[8][4];
#pragma unroll
            for (int nt = 0; nt < 8; nt++)
#pragma unroll
                for (int r = 0; r < 4; r++) sc[nt][r] = 0.f;
#pragma unroll
            for (int ks = 0; ks < 4; ks++) {
#pragma unroll
                for (int nt = 0; nt < 8; nt++) {
                    const unsigned short* p = KH + (nt*8 + g) * 72 + ks*16 + t*2;
                    uint32_t bh[2] = { *(const uint32_t*)(p), *(const uint32_t*)(p + 8) };
                    const unsigned short* q = KL + (nt*8 + g) * 72 + ks*16 + t*2;
                    uint32_t bl[2] = { *(const uint32_t*)(q), *(const uint32_t*)(q + 8) };
                    mma16816(sc[nt], qfh[ks], bh);
                    mma16816(sc[nt], qfh[ks], bl);
                    mma16816(sc[nt], qfl[ks], bh);
                }
            }

            // ---- softcap + causal mask ----
            const bool needmask = (kt * 64 + 63 > rb);
#pragma unroll
            for (int nt = 0; nt < 8; nt++) {
#pragma unroll
                for (int r = 0; r < 4; r++) {
                    float d = sc[nt][r];
                    float z = d * 0.0025f, z2 = z * z;
                    float pq = 1.f + z2*(-0.33333334f + z2*(0.13333334f - z2*0.05396825f));
                    float v = d * 0.125f * pq;           // 50*tanh(d/400)
                    if (needmask) {
                        int col = kt*64 + nt*8 + (t<<1) + (r & 1);
                        int row = rb + g + ((r >> 1) << 3);
                        if (col > row) v = -1e30f;
                    }
                    sc[nt][r] = v;
                }
            }

            // ---- online softmax ----
            float tm0 = -1e30f, tm1 = -1e30f;
#pragma unroll
            for (int nt = 0; nt < 8; nt++) {
                tm0 = fmaxf(tm0, fmaxf(sc[nt][0], sc[nt][1]));
                tm1 = fmaxf(tm1, fmaxf(sc[nt][2], sc[nt][3]));
            }
            tm0 = fmaxf(tm0, __shfl_xor_sync(0xffffffffu, tm0, 1));
            tm0 = fmaxf(tm0, __shfl_xor_sync(0xffffffffu, tm0, 2));
            tm1 = fmaxf(tm1, __shfl_xor_sync(0xffffffffu, tm1, 1));
            tm1 = fmaxf(tm1, __shfl_xor_sync(0xffffffffu, tm1, 2));
            float nm0 = fmaxf(m0, tm0), nm1 = fmaxf(m1, tm1);
            float a0 = __expf(m0 - nm0), a1 = __expf(m1 - nm1);
            m0 = nm0; m1 = nm1;
            float rs0 = 0.f, rs1 = 0.f;
#pragma unroll
            for (int nt = 0; nt < 8; nt++) {
                sc[nt][0] = __expf(sc[nt][0] - nm0);
                sc[nt][1] = __expf(sc[nt][1] - nm0);
                sc[nt][2] = __expf(sc[nt][2] - nm1);
                sc[nt][3] = __expf(sc[nt][3] - nm1);
                rs0 += sc[nt][0] + sc[nt][1];
                rs1 += sc[nt][2] + sc[nt][3];
            }
            rs0 += __shfl_xor_sync(0xffffffffu, rs0, 1);
            rs0 += __shfl_xor_sync(0xffffffffu, rs0, 2);
            rs1 += __shfl_xor_sync(0xffffffffu, rs1, 1);
            rs1 += __shfl_xor_sync(0xffffffffu, rs1, 2);
            l0 = l0 * a0 + rs0;
            l1 = l1 * a1 + rs1;
#pragma unroll
            for (int nt = 0; nt < 8; nt++) {
                oac[nt][0] *= a0; oac[nt][1] *= a0;
                oac[nt][2] *= a1; oac[nt][3] *= a1;
            }

            // ---- O += P V (3-term; P frags direct from accumulators) ----
#pragma unroll
            for (int ks = 0; ks < 4; ks++) {
                uint32_t pha[4], pla[4];
                packhl(sc[2*ks][0],   sc[2*ks][1],   pha[0], pla[0]);
                packhl(sc[2*ks][2],   sc[2*ks][3],   pha[1], pla[1]);
                packhl(sc[2*ks+1][0], sc[2*ks+1][1], pha[2], pla[2]);
                packhl(sc[2*ks+1][2], sc[2*ks+1][3], pha[3], pla[3]);
#pragma unroll
                for (int nt = 0; nt < 8; nt++) {
                    const unsigned short* p = VH + (nt*8 + g) * 72 + ks*16 + t*2;
                    uint32_t vh[2] = { *(const uint32_t*)(p), *(const uint32_t*)(p + 8) };
                    const unsigned short* q = VL + (nt*8 + g) * 72 + ks*16 + t*2;
                    uint32_t vl[2] = { *(const uint32_t*)(q), *(const uint32_t*)(q + 8) };
                    mma16816(oac[nt], pha, vh);
                    mma16816(oac[nt], pha, vl);
                    mma16816(oac[nt], pla, vh);
                }
            }
        }
        __syncthreads();
    }

    // ---- epilogue: normalize, split hi/lo, store to g_ah/g_al ----
    float i0 = 1.f / l0, i1 = 1.f / l1;
    size_t r0 = ((size_t)b * Ss + rb + g) * 2048;
    size_t r1 = ((size_t)b * Ss + rb + 8 + g) * 2048;
#pragma unroll
    for (int nt = 0; nt < 8; nt++) {
        int col = gp * 64 + nt * 8 + t * 2;
        uint32_t ph, pl;
        packhl(oac[nt][0] * i0, oac[nt][1] * i0, ph, pl);
        *(uint32_t*)&g_ah[r0 + col] = ph;
        *(uint32_t*)&g_al[r0 + col] = pl;
        packhl(oac[nt][2] * i1, oac[nt][3] * i1, ph, pl);
        *(uint32_t*)&g_ah[r1 + col] = ph;
        *(uint32_t*)&g_al[r1 + col] = pl;
    }
}

// ---------------- launch ---------------------------------------------------
extern "C" void kernel_launch(void* const* d_in, const int* in_sizes, int n_in,
                              void* d_out, int out_size)
{
    const float* x  = (const float*)d_in[0];
    const float* wq = (const float*)d_in[1];
    const float* wk = (const float*)d_in[2];
    const float* wv = (const float*)d_in[3];
    const float* wo = (const float*)d_in[4];
    const float* qn = (const float*)d_in[5];
    const float* kn = (const float*)d_in[6];
    const int* pos  = (const int*)d_in[7];
    float* out = (float*)d_out;

    float* qkv;
    cudaGetSymbolAddress((void**)&qkv, g_qkv);
    unsigned short *xh, *xl, *wh, *wl, *oh, *ol, *ah, *al;
    cudaGetSymbolAddress((void**)&xh, g_xh);  cudaGetSymbolAddress((void**)&xl, g_xl);
    cudaGetSymbolAddress((void**)&wh, g_wh);  cudaGetSymbolAddress((void**)&wl, g_wl);
    cudaGetSymbolAddress((void**)&oh, g_oh);  cudaGetSymbolAddress((void**)&ol, g_ol);
    cudaGetSymbolAddress((void**)&ah, g_ah);  cudaGetSymbolAddress((void**)&al, g_al);

    cudaFuncSetAttribute(gemm_mma, cudaFuncAttributeMaxDynamicSharedMemorySize, GEMM_SMEM);
    cudaFuncSetAttribute(attn_mma, cudaFuncAttributeMaxDynamicSharedMemorySize, ATT_SMEM);

    // 0) split fp32 -> bf16 hi/lo
    split_hl<<<8192, 256>>>((const float4*)x,  (uint2*)xh, (uint2*)xl, 2097152);
    split_hl<<<4096, 256>>>((const float4*)wq, (uint2*)wh, (uint2*)wl, 1048576);
    split_hl<<<1024, 256>>>((const float4*)wk, (uint2*)(wh + 4194304), (uint2*)(wl + 4194304), 262144);
    split_hl<<<1024, 256>>>((const float4*)wv, (uint2*)(wh + 5242880), (uint2*)(wl + 5242880), 262144);
    split_hl<<<4096, 256>>>((const float4*)wo, (uint2*)oh, (uint2*)ol, 1048576);

    // 1) QKV projection (HMMA)
    gemm_mma<<<dim3(24, 32), 256, GEMM_SMEM>>>(xh, xl, wh, wl, qkv, Dd, NTOT);

    // 2) rmsnorm + rope -> bf16 hi/lo q/k/vt
    norm_rope<<<Mtot, 256>>>(qn, kn, pos);

    // 3) MMA flash attention -> g_ah/g_al
    attn_mma<<<dim3(64, 16), 256, ATT_SMEM>>>();

    // 4) output projection (HMMA)
    gemm_mma<<<dim3(16, 32), 256, GEMM_SMEM>>>(ah, al, oh, ol, out, Dd, Dd);
}

// round 5
// speedup vs baseline: 2.5697x; 1.0084x over previous
#include <cuda_runtime.h>
#include <cuda_bf16.h>
#include <cstdint>

#define Bb 2
#define Ss 2048
#define Dd 2048
#define KVH 8
#define QPG 4
#define HD 64
#define Mtot (Bb*Ss)            // 4096
#define NQ (KVH*QPG*HD)         // 2048
#define NKV (KVH*HD)            // 512
#define NTOT (NQ + 2*NKV)       // 3072

// ---------------- scratch (module-load static, no runtime allocs) ----------
__device__ float g_qkv[(size_t)Mtot * NTOT];

__device__ unsigned short g_xh[(size_t)Mtot*Dd], g_xl[(size_t)Mtot*Dd];
__device__ unsigned short g_wh[(size_t)NTOT*Dd], g_wl[(size_t)NTOT*Dd];
__device__ unsigned short g_oh[(size_t)Dd*NQ],  g_ol[(size_t)Dd*NQ];
__device__ unsigned short g_ah[(size_t)Mtot*NQ], g_al[(size_t)Mtot*NQ];
__device__ unsigned short g_qh[(size_t)64*Ss*HD], g_ql[(size_t)64*Ss*HD];   // [head][s][h]
__device__ unsigned short g_kh[(size_t)16*Ss*HD], g_kl[(size_t)16*Ss*HD];   // [bg][s][h]
__device__ unsigned short g_vth[(size_t)16*HD*Ss], g_vtl[(size_t)16*HD*Ss]; // [bg][h][s]

// ---------------- helpers ---------------------------------------------------
__device__ __forceinline__ uint32_t s2u(const void* p){
    uint32_t a;
    asm("{ .reg .u64 t; cvta.to.shared.u64 t, %1; cvt.u32.u64 %0, t; }":"=r"(a):"l"(p));
    return a;
}
__device__ __forceinline__ void cp16(uint32_t d, const void* g){
    asm volatile("cp.async.cg.shared.global [%0], [%1], 16;" :: "r"(d), "l"(g));
}
__device__ __forceinline__ void ldm4(uint32_t* r, uint32_t addr){
    asm volatile("ldmatrix.sync.aligned.m8n8.x4.shared.b16 {%0,%1,%2,%3}, [%4];"
        : "=r"(r[0]), "=r"(r[1]), "=r"(r[2]), "=r"(r[3]) : "r"(addr));
}
__device__ __forceinline__ void mma16816(float* c, const uint32_t* a, const uint32_t* b){
    asm volatile("mma.sync.aligned.m16n8k16.row.col.f32.bf16.bf16.f32 "
        "{%0,%1,%2,%3}, {%4,%5,%6,%7}, {%8,%9}, {%0,%1,%2,%3};"
        : "+f"(c[0]), "+f"(c[1]), "+f"(c[2]), "+f"(c[3])
        : "r"(a[0]), "r"(a[1]), "r"(a[2]), "r"(a[3]), "r"(b[0]), "r"(b[1]));
}
__device__ __forceinline__ void splitf(float x, unsigned short& h, unsigned short& l){
    __nv_bfloat16 hb = __float2bfloat16(x);
    float r = x - __bfloat162float(hb);
    __nv_bfloat16 lb = __float2bfloat16(r);
    h = *(unsigned short*)&hb; l = *(unsigned short*)&lb;
}
__device__ __forceinline__ void packhl(float lo, float hi, uint32_t& ph, uint32_t& pl){
    asm("cvt.rn.bf16x2.f32 %0, %1, %2;" : "=r"(ph) : "f"(hi), "f"(lo));
    float flo = __uint_as_float(ph << 16);
    float fhi = __uint_as_float(ph & 0xFFFF0000u);
    asm("cvt.rn.bf16x2.f32 %0, %1, %2;" : "=r"(pl) : "f"(hi - fhi), "f"(lo - flo));
}

// ---------------- fp32 -> bf16 hi/lo split ---------------------------------
__global__ __launch_bounds__(256) void split_hl(const float4* __restrict__ s,
        uint2* __restrict__ hi, uint2* __restrict__ lo, int n4)
{
    int i = blockIdx.x*blockDim.x + threadIdx.x;
    if (i >= n4) return;
    float4 v = s[i];
    float f[4] = {v.x, v.y, v.z, v.w};
    unsigned short h[4], l[4];
#pragma unroll
    for (int j = 0; j < 4; j++) splitf(f[j], h[j], l[j]);
    hi[i] = make_uint2((uint32_t)h[0] | ((uint32_t)h[1]<<16),
                       (uint32_t)h[2] | ((uint32_t)h[3]<<16));
    lo[i] = make_uint2((uint32_t)l[0] | ((uint32_t)l[1]<<16),
                       (uint32_t)l[2] | ((uint32_t)l[3]<<16));
}

// ---------------- HMMA GEMM: ldmatrix frags + 3-stage cp.async -------------
#define T_ELEMS (128*40)
#define STG_ELEMS (4*T_ELEMS)
#define GEMM_SMEM (3*STG_ELEMS*2)   // 122880 bytes

__global__ __launch_bounds__(256, 1) void gemm_mma(
    const unsigned short* __restrict__ Ah, const unsigned short* __restrict__ Al,
    const unsigned short* __restrict__ Bh, const unsigned short* __restrict__ Bl,
    float* __restrict__ C, int Kd, int ldc)
{
    extern __shared__ unsigned short sm[];
    const int tid = threadIdx.x, lane = tid & 31, wid = tid >> 5;
    const int wm = wid >> 2, wn = wid & 3;
    const int g = lane >> 2, t = lane & 3;
    const int Mb = blockIdx.y * 128, Nb = blockIdx.x * 128;
    const int NC = Kd >> 5;

    float acc[4][4][4];
#pragma unroll
    for (int mt = 0; mt < 4; mt++)
#pragma unroll
        for (int nt = 0; nt < 4; nt++)
#pragma unroll
            for (int r = 0; r < 4; r++) acc[mt][nt][r] = 0.f;

    const int lrow = tid >> 1;
    const int cb   = (tid & 1) * 2;

    auto prefetch = [&](int c){
        unsigned short* s = sm + (c % 3) * STG_ELEMS;
        const int k0 = c << 5;
        const size_t ga = (size_t)(Mb + lrow) * Kd + k0;
        const size_t gb = (size_t)(Nb + lrow) * Kd + k0;
#pragma unroll
        for (int ch = cb; ch < cb + 2; ch++){
            uint32_t so = lrow * 40 + ch * 8;
            cp16(s2u(s + so),              Ah + ga + ch * 8);
            cp16(s2u(s + T_ELEMS   + so),  Al + ga + ch * 8);
            cp16(s2u(s + 2*T_ELEMS + so),  Bh + gb + ch * 8);
            cp16(s2u(s + 3*T_ELEMS + so),  Bl + gb + ch * 8);
        }
        asm volatile("cp.async.commit_group;" ::: "memory");
    };

    // ldmatrix lane-address components
    const int a_row = wm*64 + ((lane>>3)&1)*8 + (lane&7);   // + mt*16
    const int a_kof = (lane>>4)*8;                          // + kk*16
    const int b_row = wn*32 + ((lane>>4)&1)*8 + (lane&7);   // + np*16
    const int b_kof = ((lane>>3)&1)*8;                      // + kk*16

    prefetch(0);
    prefetch(1);
    for (int c = 0; c < NC; c++) {
        if (c + 2 < NC) { prefetch(c + 2); asm volatile("cp.async.wait_group 2;" ::: "memory"); }
        else if (c + 1 < NC) { asm volatile("cp.async.wait_group 1;" ::: "memory"); }
        else { asm volatile("cp.async.wait_group 0;" ::: "memory"); }
        __syncthreads();

        const unsigned short* s = sm + (c % 3) * STG_ELEMS;
#pragma unroll
        for (int kk = 0; kk < 2; kk++) {
            const int ak = kk*16 + a_kof, bk = kk*16 + b_kof;
            uint32_t ah[4][4], al[4][4], bh[8], bl[8];
#pragma unroll
            for (int mt = 0; mt < 4; mt++) {
                ldm4(ah[mt], s2u(s + (a_row + mt*16) * 40 + ak));
                ldm4(al[mt], s2u(s + T_ELEMS + (a_row + mt*16) * 40 + ak));
            }
#pragma unroll
            for (int np = 0; np < 2; np++) {
                ldm4(&bh[np*4], s2u(s + 2*T_ELEMS + (b_row + np*16) * 40 + bk));
                ldm4(&bl[np*4], s2u(s + 3*T_ELEMS + (b_row + np*16) * 40 + bk));
            }
#pragma unroll
            for (int mt = 0; mt < 4; mt++)
#pragma unroll
                for (int nt = 0; nt < 4; nt++) {
                    mma16816(acc[mt][nt], ah[mt], &bh[nt*2]);
                    mma16816(acc[mt][nt], ah[mt], &bl[nt*2]);
                    mma16816(acc[mt][nt], al[mt], &bh[nt*2]);
                }
        }
        __syncthreads();
    }

#pragma unroll
    for (int mt = 0; mt < 4; mt++) {
        int row = Mb + wm*64 + mt*16 + g;
#pragma unroll
        for (int nt = 0; nt < 4; nt++) {
            int col = Nb + wn*32 + nt*8 + t*2;
            *(float2*)&C[(size_t)row * ldc + col] =
                make_float2(acc[mt][nt][0], acc[mt][nt][1]);
            *(float2*)&C[(size_t)(row + 8) * ldc + col] =
                make_float2(acc[mt][nt][2], acc[mt][nt][3]);
        }
    }
}

// ---------------- RMSNorm + partial RoPE -> bf16 hi/lo scatter -------------
__global__ __launch_bounds__(256) void norm_rope(
    const float* __restrict__ qn, const float* __restrict__ kn,
    const int* __restrict__ pos_ids)
{
    int m = blockIdx.x;
    int b = m / Ss, s = m % Ss;
    int warp = threadIdx.x >> 5, lane = threadIdx.x & 31;
    float pos = (float)pos_ids[s];

    for (int iv = warp; iv < 48; iv += 8) {
        const float* src = g_qkv + (size_t)m * NTOT + iv * 64;
        float x1 = src[lane], x2 = src[lane + 32];
        if (iv < 40) {
            float ssum = x1 * x1 + x2 * x2;
#pragma unroll
            for (int o = 16; o >= 1; o >>= 1)
                ssum += __shfl_xor_sync(0xffffffffu, ssum, o);
            float inv = rsqrtf(ssum * (1.f / 64.f) + 1e-5f);
            const float* w = (iv < 32) ? qn : kn;
            x1 = x1 * inv * w[lane];
            x2 = x2 * inv * w[lane + 32];
            float invf = (lane < 16) ? exp2f(-0.625f * (float)lane) : 0.f;
            float f = pos * invf;
            float sn = sinf(f), cs = cosf(f);
            float o1 = x1 * cs - x2 * sn;
            float o2 = x2 * cs + x1 * sn;
            x1 = o1; x2 = o2;
        }
        unsigned short h1, l1, h2, l2;
        splitf(x1, h1, l1); splitf(x2, h2, l2);
        if (iv < 32) {
            size_t base = ((size_t)(b * 32 + iv) * Ss + s) * HD;
            g_qh[base + lane] = h1;      g_ql[base + lane] = l1;
            g_qh[base + lane + 32] = h2; g_ql[base + lane + 32] = l2;
        } else if (iv < 40) {
            size_t base = ((size_t)(b * KVH + (iv - 32)) * Ss + s) * HD;
            g_kh[base + lane] = h1;      g_kl[base + lane] = l1;
            g_kh[base + lane + 32] = h2; g_kl[base + lane + 32] = l2;
        } else {
            size_t base = (size_t)(b * KVH + (iv - 40)) * HD * Ss;
            g_vth[base + (size_t)lane * Ss + s] = h1;
            g_vtl[base + (size_t)lane * Ss + s] = l1;
            g_vth[base + (size_t)(lane + 32) * Ss + s] = h2;
            g_vtl[base + (size_t)(lane + 32) * Ss + s] = l2;
        }
    }
}

// ---------------- MMA flash attention (ldmatrix frags) ---------------------
#define QT (128*72)
#define KT (64*72)
#define AST (4*KT)
#define ATT_SMEM ((2*QT + 2*AST)*2)

__global__ __launch_bounds__(256, 1) void attn_mma()
{
    extern __shared__ unsigned short sm[];
    const int tid = threadIdx.x, lane = tid & 31, wm = tid >> 5;
    const int g = lane >> 2, t = lane & 3;
    const int head = blockIdx.x;
    const int qb = 15 - (int)blockIdx.y;
    const int b = head >> 5, gp = head & 31, kvg = gp >> 2;
    const int rb = qb * 128 + wm * 16;

    const unsigned short* Qh = g_qh + ((size_t)head * Ss + qb * 128) * HD;
    const unsigned short* Ql = g_ql + ((size_t)head * Ss + qb * 128) * HD;
    const unsigned short* Kh = g_kh + (size_t)(b * KVH + kvg) * Ss * HD;
    const unsigned short* Kl = g_kl + (size_t)(b * KVH + kvg) * Ss * HD;
    const unsigned short* Vth = g_vth + (size_t)(b * KVH + kvg) * HD * Ss;
    const unsigned short* Vtl = g_vtl + (size_t)(b * KVH + kvg) * HD * Ss;

    unsigned short* QH = sm;
    unsigned short* QL = sm + QT;

    {
        int row = tid >> 1, cbq = (tid & 1) * 4;
#pragma unroll
        for (int c = cbq; c < cbq + 4; c++) {
            uint32_t so = row * 72 + c * 8;
            cp16(s2u(QH + so), Qh + row * 64 + c * 8);
            cp16(s2u(QL + so), Ql + row * 64 + c * 8);
        }
        asm volatile("cp.async.commit_group;" ::: "memory");
    }

    auto prefetchKV = [&](int kt){
        unsigned short* st = sm + 2*QT + (kt & 1) * AST;
        int row = tid >> 2, cb2 = (tid & 3) * 2;
#pragma unroll
        for (int c = cb2; c < cb2 + 2; c++) {
            uint32_t so = row * 72 + c * 8;
            size_t ofk = (size_t)(kt * 64 + row) * HD + c * 8;
            size_t ofv = (size_t)row * Ss + kt * 64 + c * 8;
            cp16(s2u(st +        so), Kh  + ofk);
            cp16(s2u(st +   KT + so), Kl  + ofk);
            cp16(s2u(st + 2*KT + so), Vth + ofv);
            cp16(s2u(st + 3*KT + so), Vtl + ofv);
        }
        asm volatile("cp.async.commit_group;" ::: "memory");
    };

    prefetchKV(0);

    const int ktmax = 2 * qb + 1;
    float m0 = -1e30f, m1 = -1e30f, l0 = 0.f, l1 = 0.f;
    float oac[8][4];
#pragma unroll
    for (int nt = 0; nt < 8; nt++)
#pragma unroll
        for (int r = 0; r < 4; r++) oac[nt][r] = 0.f;
    uint32_t qfh[4][4], qfl[4][4];

    // ldmatrix lane-address components (B-frag style, stride 72)
    const int n_row = ((lane>>4)&1)*8 + (lane&7);   // + np*16
    const int n_kof = ((lane>>3)&1)*8;              // + ks*16

    for (int kt = 0; kt <= ktmax; kt++) {
        if (kt < ktmax) {
            prefetchKV(kt + 1);
            asm volatile("cp.async.wait_group 1;" ::: "memory");
        } else {
            asm volatile("cp.async.wait_group 0;" ::: "memory");
        }
        __syncthreads();

        if (kt == 0) {   // Q fragments via ldmatrix (A-frag style)
            const int qa_row = wm*16 + ((lane>>3)&1)*8 + (lane&7);
            const int qa_kof = (lane>>4)*8;
#pragma unroll
            for (int ks = 0; ks < 4; ks++) {
                ldm4(qfh[ks], s2u(QH + qa_row * 72 + ks*16 + qa_kof));
                ldm4(qfl[ks], s2u(QL + qa_row * 72 + ks*16 + qa_kof));
            }
        }

        if (kt * 64 <= rb + 15) {
            const unsigned short* KH = sm + 2*QT + (kt & 1) * AST;
            const unsigned short* KL = KH + KT;
            const unsigned short* VH = KH + 2*KT;
            const unsigned short* VL = KH + 3*KT;

            // ---- S = Q K^T (3-term) ----
            float sc[8][4];
#pragma unroll
            for (int nt = 0; nt < 8; nt++)
#pragma unroll
                for (int r = 0; r < 4; r++) sc[nt][r] = 0.f;
#pragma unroll
            for (int ks = 0; ks < 4; ks++) {
                uint32_t bh[16], bl[16];
#pragma unroll
                for (int np = 0; np < 4; np++) {
                    uint32_t so = (np*16 + n_row) * 72 + ks*16 + n_kof;
                    ldm4(&bh[np*4], s2u(KH + so));
                    ldm4(&bl[np*4], s2u(KL + so));
                }
#pragma unroll
                for (int nt = 0; nt < 8; nt++) {
                    mma16816(sc[nt], qfh[ks], &bh[nt*2]);
                    mma16816(sc[nt], qfh[ks], &bl[nt*2]);
                    mma16816(sc[nt], qfl[ks], &bh[nt*2]);
                }
            }

            // ---- softcap + causal mask ----
            const bool needmask = (kt * 64 + 63 > rb);
#pragma unroll
            for (int nt = 0; nt < 8; nt++) {
#pragma unroll
                for (int r = 0; r < 4; r++) {
                    float d = sc[nt][r];
                    float z = d * 0.0025f, z2 = z * z;
                    float pq = 1.f + z2*(-0.33333334f + z2*(0.13333334f - z2*0.05396825f));
                    float v = d * 0.125f * pq;
                    if (needmask) {
                        int col = kt*64 + nt*8 + (t<<1) + (r & 1);
                        int row = rb + g + ((r >> 1) << 3);
                        if (col > row) v = -1e30f;
                    }
                    sc[nt][r] = v;
                }
            }

            // ---- online softmax ----
            float tm0 = -1e30f, tm1 = -1e30f;
#pragma unroll
            for (int nt = 0; nt < 8; nt++) {
                tm0 = fmaxf(tm0, fmaxf(sc[nt][0], sc[nt][1]));
                tm1 = fmaxf(tm1, fmaxf(sc[nt][2], sc[nt][3]));
            }
            tm0 = fmaxf(tm0, __shfl_xor_sync(0xffffffffu, tm0, 1));
            tm0 = fmaxf(tm0, __shfl_xor_sync(0xffffffffu, tm0, 2));
            tm1 = fmaxf(tm1, __shfl_xor_sync(0xffffffffu, tm1, 1));
            tm1 = fmaxf(tm1, __shfl_xor_sync(0xffffffffu, tm1, 2));
            float nm0 = fmaxf(m0, tm0), nm1 = fmaxf(m1, tm1);
            float a0 = __expf(m0 - nm0), a1 = __expf(m1 - nm1);
            m0 = nm0; m1 = nm1;
            float rs0 = 0.f, rs1 = 0.f;
#pragma unroll
            for (int nt = 0; nt < 8; nt++) {
                sc[nt][0] = __expf(sc[nt][0] - nm0);
                sc[nt][1] = __expf(sc[nt][1] - nm0);
                sc[nt][2] = __expf(sc[nt][2] - nm1);
                sc[nt][3] = __expf(sc[nt][3] - nm1);
                rs0 += sc[nt][0] + sc[nt][1];
                rs1 += sc[nt][2] + sc[nt][3];
            }
            rs0 += __shfl_xor_sync(0xffffffffu, rs0, 1);
            rs0 += __shfl_xor_sync(0xffffffffu, rs0, 2);
            rs1 += __shfl_xor_sync(0xffffffffu, rs1, 1);
            rs1 += __shfl_xor_sync(0xffffffffu, rs1, 2);
            l0 = l0 * a0 + rs0;
            l1 = l1 * a1 + rs1;
#pragma unroll
            for (int nt = 0; nt < 8; nt++) {
                oac[nt][0] *= a0; oac[nt][1] *= a0;
                oac[nt][2] *= a1; oac[nt][3] *= a1;
            }

            // ---- O += P V (3-term) ----
#pragma unroll
            for (int ks = 0; ks < 4; ks++) {
                uint32_t pha[4], pla[4];
                packhl(sc[2*ks][0],   sc[2*ks][1],   pha[0], pla[0]);
                packhl(sc[2*ks][2],   sc[2*ks][3],   pha[1], pla[1]);
                packhl(sc[2*ks+1][0], sc[2*ks+1][1], pha[2], pla[2]);
                packhl(sc[2*ks+1][2], sc[2*ks+1][3], pha[3], pla[3]);
                uint32_t vh[16], vl[16];
#pragma unroll
                for (int np = 0; np < 4; np++) {
                    uint32_t so = (np*16 + n_row) * 72 + ks*16 + n_kof;
                    ldm4(&vh[np*4], s2u(VH + so));
                    ldm4(&vl[np*4], s2u(VL + so));
                }
#pragma unroll
                for (int nt = 0; nt < 8; nt++) {
                    mma16816(oac[nt], pha, &vh[nt*2]);
                    mma16816(oac[nt], pha, &vl[nt*2]);
                    mma16816(oac[nt], pla, &vh[nt*2]);
                }
            }
        }
        __syncthreads();
    }

    float i0 = 1.f / l0, i1 = 1.f / l1;
    size_t r0 = ((size_t)b * Ss + rb + g) * 2048;
    size_t r1 = ((size_t)b * Ss + rb + 8 + g) * 2048;
#pragma unroll
    for (int nt = 0; nt < 8; nt++) {
        int col = gp * 64 + nt * 8 + t * 2;
        uint32_t ph, pl;
        packhl(oac[nt][0] * i0, oac[nt][1] * i0, ph, pl);
        *(uint32_t*)&g_ah[r0 + col] = ph;
        *(uint32_t*)&g_al[r0 + col] = pl;
        packhl(oac[nt][2] * i1, oac[nt][3] * i1, ph, pl);
        *(uint32_t*)&g_ah[r1 + col] = ph;
        *(uint32_t*)&g_al[r1 + col] = pl;
    }
}

// ---------------- launch ---------------------------------------------------
extern "C" void kernel_launch(void* const* d_in, const int* in_sizes, int n_in,
                              void* d_out, int out_size)
{
    const float* x  = (const float*)d_in[0];
    const float* wq = (const float*)d_in[1];
    const float* wk = (const float*)d_in[2];
    const float* wv = (const float*)d_in[3];
    const float* wo = (const float*)d_in[4];
    const float* qn = (const float*)d_in[5];
    const float* kn = (const float*)d_in[6];
    const int* pos  = (const int*)d_in[7];
    float* out = (float*)d_out;

    float* qkv;
    cudaGetSymbolAddress((void**)&qkv, g_qkv);
    unsigned short *xh, *xl, *wh, *wl, *oh, *ol, *ah, *al;
    cudaGetSymbolAddress((void**)&xh, g_xh);  cudaGetSymbolAddress((void**)&xl, g_xl);
    cudaGetSymbolAddress((void**)&wh, g_wh);  cudaGetSymbolAddress((void**)&wl, g_wl);
    cudaGetSymbolAddress((void**)&oh, g_oh);  cudaGetSymbolAddress((void**)&ol, g_ol);
    cudaGetSymbolAddress((void**)&ah, g_ah);  cudaGetSymbolAddress((void**)&al, g_al);

    cudaFuncSetAttribute(gemm_mma, cudaFuncAttributeMaxDynamicSharedMemorySize, GEMM_SMEM);
    cudaFuncSetAttribute(attn_mma, cudaFuncAttributeMaxDynamicSharedMemorySize, ATT_SMEM);

    split_hl<<<8192, 256>>>((const float4*)x,  (uint2*)xh, (uint2*)xl, 2097152);
    split_hl<<<4096, 256>>>((const float4*)wq, (uint2*)wh, (uint2*)wl, 1048576);
    split_hl<<<1024, 256>>>((const float4*)wk, (uint2*)(wh + 4194304), (uint2*)(wl + 4194304), 262144);
    split_hl<<<1024, 256>>>((const float4*)wv, (uint2*)(wh + 5242880), (uint2*)(wl + 5242880), 262144);
    split_hl<<<4096, 256>>>((const float4*)wo, (uint2*)oh, (uint2*)ol, 1048576);

    gemm_mma<<<dim3(24, 32), 256, GEMM_SMEM>>>(xh, xl, wh, wl, qkv, Dd, NTOT);
    norm_rope<<<Mtot, 256>>>(qn, kn, pos);
    attn_mma<<<dim3(64, 16), 256, ATT_SMEM>>>();
    gemm_mma<<<dim3(16, 32), 256, GEMM_SMEM>>>(ah, al, oh, ol, out, Dd, Dd);
}

// round 6
// speedup vs baseline: 2.7847x; 1.0837x over previous
#include <cuda_runtime.h>
#include <cuda_bf16.h>
#include <cstdint>

#define Bb 2
#define Ss 2048
#define Dd 2048
#define KVH 8
#define QPG 4
#define HD 64
#define Mtot (Bb*Ss)            // 4096
#define NQ (KVH*QPG*HD)         // 2048
#define NKV (KVH*HD)            // 512
#define NTOT (NQ + 2*NKV)       // 3072

// ---------------- scratch (module-load static, no runtime allocs) ----------
__device__ float g_qkv[(size_t)Mtot * NTOT];

__device__ unsigned short g_xh[(size_t)Mtot*Dd], g_xl[(size_t)Mtot*Dd];
__device__ unsigned short g_wh[(size_t)NTOT*Dd], g_wl[(size_t)NTOT*Dd];
__device__ unsigned short g_oh[(size_t)Dd*NQ],  g_ol[(size_t)Dd*NQ];
__device__ unsigned short g_ah[(size_t)Mtot*NQ], g_al[(size_t)Mtot*NQ];
__device__ unsigned short g_qh[(size_t)64*Ss*HD], g_ql[(size_t)64*Ss*HD];   // [head][s][h]
__device__ unsigned short g_kh[(size_t)16*Ss*HD], g_kl[(size_t)16*Ss*HD];   // [bg][s][h]
__device__ unsigned short g_vth[(size_t)16*HD*Ss], g_vtl[(size_t)16*HD*Ss]; // [bg][h][s]

// ---------------- helpers ---------------------------------------------------
__device__ __forceinline__ uint32_t s2u(const void* p){
    uint32_t a;
    asm("{ .reg .u64 t; cvta.to.shared.u64 t, %1; cvt.u32.u64 %0, t; }":"=r"(a):"l"(p));
    return a;
}
__device__ __forceinline__ void cp16(uint32_t d, const void* g){
    asm volatile("cp.async.cg.shared.global [%0], [%1], 16;" :: "r"(d), "l"(g));
}
__device__ __forceinline__ void ldm4(uint32_t* r, uint32_t addr){
    asm volatile("ldmatrix.sync.aligned.m8n8.x4.shared.b16 {%0,%1,%2,%3}, [%4];"
        : "=r"(r[0]), "=r"(r[1]), "=r"(r[2]), "=r"(r[3]) : "r"(addr));
}
__device__ __forceinline__ void mma16816(float* c, const uint32_t* a, const uint32_t* b){
    asm volatile("mma.sync.aligned.m16n8k16.row.col.f32.bf16.bf16.f32 "
        "{%0,%1,%2,%3}, {%4,%5,%6,%7}, {%8,%9}, {%0,%1,%2,%3};"
        : "+f"(c[0]), "+f"(c[1]), "+f"(c[2]), "+f"(c[3])
        : "r"(a[0]), "r"(a[1]), "r"(a[2]), "r"(a[3]), "r"(b[0]), "r"(b[1]));
}
__device__ __forceinline__ void splitf(float x, unsigned short& h, unsigned short& l){
    __nv_bfloat16 hb = __float2bfloat16(x);
    float r = x - __bfloat162float(hb);
    __nv_bfloat16 lb = __float2bfloat16(r);
    h = *(unsigned short*)&hb; l = *(unsigned short*)&lb;
}
__device__ __forceinline__ void packhl(float lo, float hi, uint32_t& ph, uint32_t& pl){
    asm("cvt.rn.bf16x2.f32 %0, %1, %2;" : "=r"(ph) : "f"(hi), "f"(lo));
    float flo = __uint_as_float(ph << 16);
    float fhi = __uint_as_float(ph & 0xFFFF0000u);
    asm("cvt.rn.bf16x2.f32 %0, %1, %2;" : "=r"(pl) : "f"(hi - fhi), "f"(lo - flo));
}

// ---------------- fp32 -> bf16 hi/lo split ---------------------------------
__global__ __launch_bounds__(256) void split_hl(const float4* __restrict__ s,
        uint2* __restrict__ hi, uint2* __restrict__ lo, int n4)
{
    int i = blockIdx.x*blockDim.x + threadIdx.x;
    if (i >= n4) return;
    float4 v = s[i];
    float f[4] = {v.x, v.y, v.z, v.w};
    unsigned short h[4], l[4];
#pragma unroll
    for (int j = 0; j < 4; j++) splitf(f[j], h[j], l[j]);
    hi[i] = make_uint2((uint32_t)h[0] | ((uint32_t)h[1]<<16),
                       (uint32_t)h[2] | ((uint32_t)h[3]<<16));
    lo[i] = make_uint2((uint32_t)l[0] | ((uint32_t)l[1]<<16),
                       (uint32_t)l[2] | ((uint32_t)l[3]<<16));
}

// ---------------- HMMA GEMM: 512 thr, 16 warps, 128x128x32, 3-stage --------
#define T_ELEMS (128*40)
#define STG_ELEMS (4*T_ELEMS)
#define GEMM_SMEM (3*STG_ELEMS*2)   // 122880 bytes

__global__ __launch_bounds__(512, 1) void gemm_mma(
    const unsigned short* __restrict__ Ah, const unsigned short* __restrict__ Al,
    const unsigned short* __restrict__ Bh, const unsigned short* __restrict__ Bl,
    float* __restrict__ C, int Kd, int ldc)
{
    extern __shared__ unsigned short sm[];
    const int tid = threadIdx.x, lane = tid & 31, wid = tid >> 5;
    const int wm = wid >> 2, wn = wid & 3;      // 4 x 4 warp grid, 32x32 per warp
    const int g = lane >> 2, t = lane & 3;
    const int Mb = blockIdx.y * 128, Nb = blockIdx.x * 128;
    const int NC = Kd >> 5;

    float acc[2][4][4];
#pragma unroll
    for (int mt = 0; mt < 2; mt++)
#pragma unroll
        for (int nt = 0; nt < 4; nt++)
#pragma unroll
            for (int r = 0; r < 4; r++) acc[mt][nt][r] = 0.f;

    const int lrow = tid >> 2;         // 0..127
    const int lch  = tid & 3;          // 16B chunk

    auto prefetch = [&](int c){
        unsigned short* s = sm + (c % 3) * STG_ELEMS;
        const int k0 = c << 5;
        uint32_t so = lrow * 40 + lch * 8;
        size_t ga = (size_t)(Mb + lrow) * Kd + k0 + lch * 8;
        size_t gb = (size_t)(Nb + lrow) * Kd + k0 + lch * 8;
        cp16(s2u(s + so),              Ah + ga);
        cp16(s2u(s + T_ELEMS   + so),  Al + ga);
        cp16(s2u(s + 2*T_ELEMS + so),  Bh + gb);
        cp16(s2u(s + 3*T_ELEMS + so),  Bl + gb);
        asm volatile("cp.async.commit_group;" ::: "memory");
    };

    // ldmatrix lane-address components
    const int a_row = wm*32 + ((lane>>3)&1)*8 + (lane&7);   // + mt*16
    const int a_kof = (lane>>4)*8;                          // + kk*16
    const int b_row = wn*32 + ((lane>>4)&1)*8 + (lane&7);   // + np*16
    const int b_kof = ((lane>>3)&1)*8;                      // + kk*16

    prefetch(0);
    prefetch(1);
    for (int c = 0; c < NC; c++) {
        if (c + 1 < NC) { asm volatile("cp.async.wait_group 1;" ::: "memory"); }
        else            { asm volatile("cp.async.wait_group 0;" ::: "memory"); }
        __syncthreads();
        if (c + 2 < NC) prefetch(c + 2);

        const unsigned short* s = sm + (c % 3) * STG_ELEMS;
#pragma unroll
        for (int kk = 0; kk < 2; kk++) {
            const int ak = kk*16 + a_kof, bk = kk*16 + b_kof;
            uint32_t ah[2][4], al[2][4], bh[8], bl[8];
#pragma unroll
            for (int mt = 0; mt < 2; mt++) {
                ldm4(ah[mt], s2u(s + (a_row + mt*16) * 40 + ak));
                ldm4(al[mt], s2u(s + T_ELEMS + (a_row + mt*16) * 40 + ak));
            }
#pragma unroll
            for (int np = 0; np < 2; np++) {
                ldm4(&bh[np*4], s2u(s + 2*T_ELEMS + (b_row + np*16) * 40 + bk));
                ldm4(&bl[np*4], s2u(s + 3*T_ELEMS + (b_row + np*16) * 40 + bk));
            }
#pragma unroll
            for (int mt = 0; mt < 2; mt++)
#pragma unroll
                for (int nt = 0; nt < 4; nt++) {
                    mma16816(acc[mt][nt], ah[mt], &bh[nt*2]);
                    mma16816(acc[mt][nt], ah[mt], &bl[nt*2]);
                    mma16816(acc[mt][nt], al[mt], &bh[nt*2]);
                }
        }
    }

#pragma unroll
    for (int mt = 0; mt < 2; mt++) {
        int row = Mb + wm*32 + mt*16 + g;
#pragma unroll
        for (int nt = 0; nt < 4; nt++) {
            int col = Nb + wn*32 + nt*8 + t*2;
            *(float2*)&C[(size_t)row * ldc + col] =
                make_float2(acc[mt][nt][0], acc[mt][nt][1]);
            *(float2*)&C[(size_t)(row + 8) * ldc + col] =
                make_float2(acc[mt][nt][2], acc[mt][nt][3]);
        }
    }
}

// ---------------- RMSNorm + partial RoPE -> bf16 hi/lo scatter -------------
__global__ __launch_bounds__(256) void norm_rope(
    const float* __restrict__ qn, const float* __restrict__ kn,
    const int* __restrict__ pos_ids)
{
    int m = blockIdx.x;
    int b = m / Ss, s = m % Ss;
    int warp = threadIdx.x >> 5, lane = threadIdx.x & 31;
    float pos = (float)pos_ids[s];

    for (int iv = warp; iv < 48; iv += 8) {
        const float* src = g_qkv + (size_t)m * NTOT + iv * 64;
        float x1 = src[lane], x2 = src[lane + 32];
        if (iv < 40) {
            float ssum = x1 * x1 + x2 * x2;
#pragma unroll
            for (int o = 16; o >= 1; o >>= 1)
                ssum += __shfl_xor_sync(0xffffffffu, ssum, o);
            float inv = rsqrtf(ssum * (1.f / 64.f) + 1e-5f);
            const float* w = (iv < 32) ? qn : kn;
            x1 = x1 * inv * w[lane];
            x2 = x2 * inv * w[lane + 32];
            float invf = (lane < 16) ? exp2f(-0.625f * (float)lane) : 0.f;
            float f = pos * invf;
            float sn = sinf(f), cs = cosf(f);
            float o1 = x1 * cs - x2 * sn;
            float o2 = x2 * cs + x1 * sn;
            x1 = o1; x2 = o2;
        }
        unsigned short h1, l1, h2, l2;
        splitf(x1, h1, l1); splitf(x2, h2, l2);
        if (iv < 32) {
            size_t base = ((size_t)(b * 32 + iv) * Ss + s) * HD;
            g_qh[base + lane] = h1;      g_ql[base + lane] = l1;
            g_qh[base + lane + 32] = h2; g_ql[base + lane + 32] = l2;
        } else if (iv < 40) {
            size_t base = ((size_t)(b * KVH + (iv - 32)) * Ss + s) * HD;
            g_kh[base + lane] = h1;      g_kl[base + lane] = l1;
            g_kh[base + lane + 32] = h2; g_kl[base + lane + 32] = l2;
        } else {
            size_t base = (size_t)(b * KVH + (iv - 40)) * HD * Ss;
            g_vth[base + (size_t)lane * Ss + s] = h1;
            g_vtl[base + (size_t)lane * Ss + s] = l1;
            g_vth[base + (size_t)(lane + 32) * Ss + s] = h2;
            g_vtl[base + (size_t)(lane + 32) * Ss + s] = l2;
        }
    }
}

// ---------------- MMA flash attention (unchanged from R5) ------------------
#define QT (128*72)
#define KT (64*72)
#define AST (4*KT)
#define ATT_SMEM ((2*QT + 2*AST)*2)

__global__ __launch_bounds__(256, 1) void attn_mma()
{
    extern __shared__ unsigned short sm[];
    const int tid = threadIdx.x, lane = tid & 31, wm = tid >> 5;
    const int g = lane >> 2, t = lane & 3;
    const int head = blockIdx.x;
    const int qb = 15 - (int)blockIdx.y;
    const int b = head >> 5, gp = head & 31, kvg = gp >> 2;
    const int rb = qb * 128 + wm * 16;

    const unsigned short* Qh = g_qh + ((size_t)head * Ss + qb * 128) * HD;
    const unsigned short* Ql = g_ql + ((size_t)head * Ss + qb * 128) * HD;
    const unsigned short* Kh = g_kh + (size_t)(b * KVH + kvg) * Ss * HD;
    const unsigned short* Kl = g_kl + (size_t)(b * KVH + kvg) * Ss * HD;
    const unsigned short* Vth = g_vth + (size_t)(b * KVH + kvg) * HD * Ss;
    const unsigned short* Vtl = g_vtl + (size_t)(b * KVH + kvg) * HD * Ss;

    unsigned short* QH = sm;
    unsigned short* QL = sm + QT;

    {
        int row = tid >> 1, cbq = (tid & 1) * 4;
#pragma unroll
        for (int c = cbq; c < cbq + 4; c++) {
            uint32_t so = row * 72 + c * 8;
            cp16(s2u(QH + so), Qh + row * 64 + c * 8);
            cp16(s2u(QL + so), Ql + row * 64 + c * 8);
        }
        asm volatile("cp.async.commit_group;" ::: "memory");
    }

    auto prefetchKV = [&](int kt){
        unsigned short* st = sm + 2*QT + (kt & 1) * AST;
        int row = tid >> 2, cb2 = (tid & 3) * 2;
#pragma unroll
        for (int c = cb2; c < cb2 + 2; c++) {
            uint32_t so = row * 72 + c * 8;
            size_t ofk = (size_t)(kt * 64 + row) * HD + c * 8;
            size_t ofv = (size_t)row * Ss + kt * 64 + c * 8;
            cp16(s2u(st +        so), Kh  + ofk);
            cp16(s2u(st +   KT + so), Kl  + ofk);
            cp16(s2u(st + 2*KT + so), Vth + ofv);
            cp16(s2u(st + 3*KT + so), Vtl + ofv);
        }
        asm volatile("cp.async.commit_group;" ::: "memory");
    };

    prefetchKV(0);

    const int ktmax = 2 * qb + 1;
    float m0 = -1e30f, m1 = -1e30f, l0 = 0.f, l1 = 0.f;
    float oac[8][4];
#pragma unroll
    for (int nt = 0; nt < 8; nt++)
#pragma unroll
        for (int r = 0; r < 4; r++) oac[nt][r] = 0.f;
    uint32_t qfh[4][4], qfl[4][4];

    const int n_row = ((lane>>4)&1)*8 + (lane&7);
    const int n_kof = ((lane>>3)&1)*8;

    for (int kt = 0; kt <= ktmax; kt++) {
        if (kt < ktmax) {
            prefetchKV(kt + 1);
            asm volatile("cp.async.wait_group 1;" ::: "memory");
        } else {
            asm volatile("cp.async.wait_group 0;" ::: "memory");
        }
        __syncthreads();

        if (kt == 0) {
            const int qa_row = wm*16 + ((lane>>3)&1)*8 + (lane&7);
            const int qa_kof = (lane>>4)*8;
#pragma unroll
            for (int ks = 0; ks < 4; ks++) {
                ldm4(qfh[ks], s2u(QH + qa_row * 72 + ks*16 + qa_kof));
                ldm4(qfl[ks], s2u(QL + qa_row * 72 + ks*16 + qa_kof));
            }
        }

        if (kt * 64 <= rb + 15) {
            const unsigned short* KH = sm + 2*QT + (kt & 1) * AST;
            const unsigned short* KL = KH + KT;
            const unsigned short* VH = KH + 2*KT;
            const unsigned short* VL = KH + 3*KT;

            float sc[8][4];
#pragma unroll
            for (int nt = 0; nt < 8; nt++)
#pragma unroll
                for (int r = 0; r < 4; r++) sc[nt][r] = 0.f;
#pragma unroll
            for (int ks = 0; ks < 4; ks++) {
                uint32_t bh[16], bl[16];
#pragma unroll
                for (int np = 0; np < 4; np++) {
                    uint32_t so = (np*16 + n_row) * 72 + ks*16 + n_kof;
                    ldm4(&bh[np*4], s2u(KH + so));
                    ldm4(&bl[np*4], s2u(KL + so));
                }
#pragma unroll
                for (int nt = 0; nt < 8; nt++) {
                    mma16816(sc[nt], qfh[ks], &bh[nt*2]);
                    mma16816(sc[nt], qfh[ks], &bl[nt*2]);
                    mma16816(sc[nt], qfl[ks], &bh[nt*2]);
                }
            }

            const bool needmask = (kt * 64 + 63 > rb);
#pragma unroll
            for (int nt = 0; nt < 8; nt++) {
#pragma unroll
                for (int r = 0; r < 4; r++) {
                    float d = sc[nt][r];
                    float z = d * 0.0025f, z2 = z * z;
                    float pq = 1.f + z2*(-0.33333334f + z2*(0.13333334f - z2*0.05396825f));
                    float v = d * 0.125f * pq;
                    if (needmask) {
                        int col = kt*64 + nt*8 + (t<<1) + (r & 1);
                        int row = rb + g + ((r >> 1) << 3);
                        if (col > row) v = -1e30f;
                    }
                    sc[nt][r] = v;
                }
            }

            float tm0 = -1e30f, tm1 = -1e30f;
#pragma unroll
            for (int nt = 0; nt < 8; nt++) {
                tm0 = fmaxf(tm0, fmaxf(sc[nt][0], sc[nt][1]));
                tm1 = fmaxf(tm1, fmaxf(sc[nt][2], sc[nt][3]));
            }
            tm0 = fmaxf(tm0, __shfl_xor_sync(0xffffffffu, tm0, 1));
            tm0 = fmaxf(tm0, __shfl_xor_sync(0xffffffffu, tm0, 2));
            tm1 = fmaxf(tm1, __shfl_xor_sync(0xffffffffu, tm1, 1));
            tm1 = fmaxf(tm1, __shfl_xor_sync(0xffffffffu, tm1, 2));
            float nm0 = fmaxf(m0, tm0), nm1 = fmaxf(m1, tm1);
            float a0 = __expf(m0 - nm0), a1 = __expf(m1 - nm1);
            m0 = nm0; m1 = nm1;
            float rs0 = 0.f, rs1 = 0.f;
#pragma unroll
            for (int nt = 0; nt < 8; nt++) {
                sc[nt][0] = __expf(sc[nt][0] - nm0);
                sc[nt][1] = __expf(sc[nt][1] - nm0);
                sc[nt][2] = __expf(sc[nt][2] - nm1);
                sc[nt][3] = __expf(sc[nt][3] - nm1);
                rs0 += sc[nt][0] + sc[nt][1];
                rs1 += sc[nt][2] + sc[nt][3];
            }
            rs0 += __shfl_xor_sync(0xffffffffu, rs0, 1);
            rs0 += __shfl_xor_sync(0xffffffffu, rs0, 2);
            rs1 += __shfl_xor_sync(0xffffffffu, rs1, 1);
            rs1 += __shfl_xor_sync(0xffffffffu, rs1, 2);
            l0 = l0 * a0 + rs0;
            l1 = l1 * a1 + rs1;
#pragma unroll
            for (int nt = 0; nt < 8; nt++) {
                oac[nt][0] *= a0; oac[nt][1] *= a0;
                oac[nt][2] *= a1; oac[nt][3] *= a1;
            }

#pragma unroll
            for (int ks = 0; ks < 4; ks++) {
                uint32_t pha[4], pla[4];
                packhl(sc[2*ks][0],   sc[2*ks][1],   pha[0], pla[0]);
                packhl(sc[2*ks][2],   sc[2*ks][3],   pha[1], pla[1]);
                packhl(sc[2*ks+1][0], sc[2*ks+1][1], pha[2], pla[2]);
                packhl(sc[2*ks+1][2], sc[2*ks+1][3], pha[3], pla[3]);
                uint32_t vh[16], vl[16];
#pragma unroll
                for (int np = 0; np < 4; np++) {
                    uint32_t so = (np*16 + n_row) * 72 + ks*16 + n_kof;
                    ldm4(&vh[np*4], s2u(VH + so));
                    ldm4(&vl[np*4], s2u(VL + so));
                }
#pragma unroll
                for (int nt = 0; nt < 8; nt++) {
                    mma16816(oac[nt], pha, &vh[nt*2]);
                    mma16816(oac[nt], pha, &vl[nt*2]);
                    mma16816(oac[nt], pla, &vh[nt*2]);
                }
            }
        }
        __syncthreads();
    }

    float i0 = 1.f / l0, i1 = 1.f / l1;
    size_t r0 = ((size_t)b * Ss + rb + g) * 2048;
    size_t r1 = ((size_t)b * Ss + rb + 8 + g) * 2048;
#pragma unroll
    for (int nt = 0; nt < 8; nt++) {
        int col = gp * 64 + nt * 8 + t * 2;
        uint32_t ph, pl;
        packhl(oac[nt][0] * i0, oac[nt][1] * i0, ph, pl);
        *(uint32_t*)&g_ah[r0 + col] = ph;
        *(uint32_t*)&g_al[r0 + col] = pl;
        packhl(oac[nt][2] * i1, oac[nt][3] * i1, ph, pl);
        *(uint32_t*)&g_ah[r1 + col] = ph;
        *(uint32_t*)&g_al[r1 + col] = pl;
    }
}

// ---------------- launch ---------------------------------------------------
extern "C" void kernel_launch(void* const* d_in, const int* in_sizes, int n_in,
                              void* d_out, int out_size)
{
    const float* x  = (const float*)d_in[0];
    const float* wq = (const float*)d_in[1];
    const float* wk = (const float*)d_in[2];
    const float* wv = (const float*)d_in[3];
    const float* wo = (const float*)d_in[4];
    const float* qn = (const float*)d_in[5];
    const float* kn = (const float*)d_in[6];
    const int* pos  = (const int*)d_in[7];
    float* out = (float*)d_out;

    float* qkv;
    cudaGetSymbolAddress((void**)&qkv, g_qkv);
    unsigned short *xh, *xl, *wh, *wl, *oh, *ol, *ah, *al;
    cudaGetSymbolAddress((void**)&xh, g_xh);  cudaGetSymbolAddress((void**)&xl, g_xl);
    cudaGetSymbolAddress((void**)&wh, g_wh);  cudaGetSymbolAddress((void**)&wl, g_wl);
    cudaGetSymbolAddress((void**)&oh, g_oh);  cudaGetSymbolAddress((void**)&ol, g_ol);
    cudaGetSymbolAddress((void**)&ah, g_ah);  cudaGetSymbolAddress((void**)&al, g_al);

    cudaFuncSetAttribute(gemm_mma, cudaFuncAttributeMaxDynamicSharedMemorySize, GEMM_SMEM);
    cudaFuncSetAttribute(attn_mma, cudaFuncAttributeMaxDynamicSharedMemorySize, ATT_SMEM);

    split_hl<<<8192, 256>>>((const float4*)x,  (uint2*)xh, (uint2*)xl, 2097152);
    split_hl<<<4096, 256>>>((const float4*)wq, (uint2*)wh, (uint2*)wl, 1048576);
    split_hl<<<1024, 256>>>((const float4*)wk, (uint2*)(wh + 4194304), (uint2*)(wl + 4194304), 262144);
    split_hl<<<1024, 256>>>((const float4*)wv, (uint2*)(wh + 5242880), (uint2*)(wl + 5242880), 262144);
    split_hl<<<4096, 256>>>((const float4*)wo, (uint2*)oh, (uint2*)ol, 1048576);

    gemm_mma<<<dim3(24, 32), 512, GEMM_SMEM>>>(xh, xl, wh, wl, qkv, Dd, NTOT);
    norm_rope<<<Mtot, 256>>>(qn, kn, pos);
    attn_mma<<<dim3(64, 16), 256, ATT_SMEM>>>();
    gemm_mma<<<dim3(16, 32), 512, GEMM_SMEM>>>(ah, al, oh, ol, out, Dd, Dd);
}

// round 7
// speedup vs baseline: 3.6411x; 1.3076x over previous
#include <cuda_runtime.h>
#include <cuda_fp16.h>
#include <cstdint>

#define Bb 2
#define Ss 2048
#define Dd 2048
#define KVH 8
#define QPG 4
#define HD 64
#define Mtot (Bb*Ss)            // 4096
#define NQ (KVH*QPG*HD)         // 2048
#define NKV (KVH*HD)            // 512
#define NTOT (NQ + 2*NKV)       // 3072

// ---------------- scratch (module-load static, no runtime allocs) ----------
__device__ float g_qkv[(size_t)Mtot * NTOT];

__device__ unsigned short g_xh[(size_t)Mtot*Dd];                 // x fp16
__device__ unsigned short g_wh[(size_t)NTOT*Dd], g_wl[(size_t)NTOT*Dd];
__device__ unsigned short g_oh[(size_t)Dd*NQ],  g_ol[(size_t)Dd*NQ];
__device__ unsigned short g_af[(size_t)Mtot*NQ];                 // attn out fp16
__device__ unsigned short g_qh[(size_t)64*Ss*HD];                // [head][s][h]
__device__ unsigned short g_kh[(size_t)16*Ss*HD], g_kl[(size_t)16*Ss*HD];   // [bg][s][h]
__device__ unsigned short g_vth[(size_t)16*HD*Ss], g_vtl[(size_t)16*HD*Ss]; // [bg][h][s]

// ---------------- helpers ---------------------------------------------------
__device__ __forceinline__ uint32_t s2u(const void* p){
    uint32_t a;
    asm("{ .reg .u64 t; cvta.to.shared.u64 t, %1; cvt.u32.u64 %0, t; }":"=r"(a):"l"(p));
    return a;
}
__device__ __forceinline__ void cp16(uint32_t d, const void* g){
    asm volatile("cp.async.cg.shared.global [%0], [%1], 16;" :: "r"(d), "l"(g));
}
__device__ __forceinline__ void ldm4(uint32_t* r, uint32_t addr){
    asm volatile("ldmatrix.sync.aligned.m8n8.x4.shared.b16 {%0,%1,%2,%3}, [%4];"
        : "=r"(r[0]), "=r"(r[1]), "=r"(r[2]), "=r"(r[3]) : "r"(addr));
}
__device__ __forceinline__ void mma16816(float* c, const uint32_t* a, const uint32_t* b){
    asm volatile("mma.sync.aligned.m16n8k16.row.col.f32.f16.f16.f32 "
        "{%0,%1,%2,%3}, {%4,%5,%6,%7}, {%8,%9}, {%0,%1,%2,%3};"
        : "+f"(c[0]), "+f"(c[1]), "+f"(c[2]), "+f"(c[3])
        : "r"(a[0]), "r"(a[1]), "r"(a[2]), "r"(a[3]), "r"(b[0]), "r"(b[1]));
}
__device__ __forceinline__ void splith(float x, unsigned short& h, unsigned short& l){
    __half hb = __float2half(x);
    float r = x - __half2float(hb);
    __half lb = __float2half(r);
    h = *(unsigned short*)&hb; l = *(unsigned short*)&lb;
}
__device__ __forceinline__ uint32_t packh(float lo, float hi){
    uint32_t r;
    asm("cvt.rn.f16x2.f32 %0, %1, %2;" : "=r"(r) : "f"(hi), "f"(lo));
    return r;
}

// ---------------- fp32 -> fp16 hi/lo split ---------------------------------
__global__ __launch_bounds__(256) void split16(const float4* __restrict__ s,
        uint2* __restrict__ hi, uint2* __restrict__ lo, int n4)
{
    int i = blockIdx.x*blockDim.x + threadIdx.x;
    if (i >= n4) return;
    float4 v = s[i];
    float f[4] = {v.x, v.y, v.z, v.w};
    unsigned short h[4], l[4];
#pragma unroll
    for (int j = 0; j < 4; j++) splith(f[j], h[j], l[j]);
    hi[i] = make_uint2((uint32_t)h[0] | ((uint32_t)h[1]<<16),
                       (uint32_t)h[2] | ((uint32_t)h[3]<<16));
    lo[i] = make_uint2((uint32_t)l[0] | ((uint32_t)l[1]<<16),
                       (uint32_t)l[2] | ((uint32_t)l[3]<<16));
}
__global__ __launch_bounds__(256) void tohalf(const float4* __restrict__ s,
        uint2* __restrict__ hi, int n4)
{
    int i = blockIdx.x*blockDim.x + threadIdx.x;
    if (i >= n4) return;
    float4 v = s[i];
    hi[i] = make_uint2(packh(v.x, v.y), packh(v.z, v.w));
}

// ---------------- HMMA GEMM: C = A @ (Bh+Bl)^T, fp16 2-term ----------------
#define T_ELEMS (128*40)
#define STG_ELEMS (3*T_ELEMS)
#define GEMM_SMEM (3*STG_ELEMS*2)   // 92160 bytes

__global__ __launch_bounds__(512, 1) void gemm_mma(
    const unsigned short* __restrict__ A,
    const unsigned short* __restrict__ Bh, const unsigned short* __restrict__ Bl,
    float* __restrict__ C, int Kd, int ldc)
{
    extern __shared__ unsigned short sm[];
    const int tid = threadIdx.x, lane = tid & 31, wid = tid >> 5;
    const int wm = wid >> 2, wn = wid & 3;      // 4 x 4 warp grid, 32x32 per warp
    const int g = lane >> 2, t = lane & 3;
    const int Mb = blockIdx.y * 128, Nb = blockIdx.x * 128;
    const int NC = Kd >> 5;

    float acc[2][4][4];
#pragma unroll
    for (int mt = 0; mt < 2; mt++)
#pragma unroll
        for (int nt = 0; nt < 4; nt++)
#pragma unroll
            for (int r = 0; r < 4; r++) acc[mt][nt][r] = 0.f;

    const int lrow = tid >> 2;
    const int lch  = tid & 3;

    auto prefetch = [&](int c){
        unsigned short* s = sm + (c % 3) * STG_ELEMS;
        const int k0 = c << 5;
        uint32_t so = lrow * 40 + lch * 8;
        size_t ga = (size_t)(Mb + lrow) * Kd + k0 + lch * 8;
        size_t gb = (size_t)(Nb + lrow) * Kd + k0 + lch * 8;
        cp16(s2u(s + so),              A  + ga);
        cp16(s2u(s + T_ELEMS   + so),  Bh + gb);
        cp16(s2u(s + 2*T_ELEMS + so),  Bl + gb);
        asm volatile("cp.async.commit_group;" ::: "memory");
    };

    const int a_row = wm*32 + ((lane>>3)&1)*8 + (lane&7);
    const int a_kof = (lane>>4)*8;
    const int b_row = wn*32 + ((lane>>4)&1)*8 + (lane&7);
    const int b_kof = ((lane>>3)&1)*8;

    prefetch(0);
    prefetch(1);
    for (int c = 0; c < NC; c++) {
        if (c + 1 < NC) { asm volatile("cp.async.wait_group 1;" ::: "memory"); }
        else            { asm volatile("cp.async.wait_group 0;" ::: "memory"); }
        __syncthreads();
        if (c + 2 < NC) prefetch(c + 2);

        const unsigned short* s = sm + (c % 3) * STG_ELEMS;
#pragma unroll
        for (int kk = 0; kk < 2; kk++) {
            const int ak = kk*16 + a_kof, bk = kk*16 + b_kof;
            uint32_t ah[2][4], bh[8], bl[8];
#pragma unroll
            for (int mt = 0; mt < 2; mt++)
                ldm4(ah[mt], s2u(s + (a_row + mt*16) * 40 + ak));
#pragma unroll
            for (int np = 0; np < 2; np++) {
                ldm4(&bh[np*4], s2u(s + T_ELEMS   + (b_row + np*16) * 40 + bk));
                ldm4(&bl[np*4], s2u(s + 2*T_ELEMS + (b_row + np*16) * 40 + bk));
            }
#pragma unroll
            for (int mt = 0; mt < 2; mt++)
#pragma unroll
                for (int nt = 0; nt < 4; nt++) {
                    mma16816(acc[mt][nt], ah[mt], &bh[nt*2]);
                    mma16816(acc[mt][nt], ah[mt], &bl[nt*2]);
                }
        }
    }

#pragma unroll
    for (int mt = 0; mt < 2; mt++) {
        int row = Mb + wm*32 + mt*16 + g;
#pragma unroll
        for (int nt = 0; nt < 4; nt++) {
            int col = Nb + wn*32 + nt*8 + t*2;
            *(float2*)&C[(size_t)row * ldc + col] =
                make_float2(acc[mt][nt][0], acc[mt][nt][1]);
            *(float2*)&C[(size_t)(row + 8) * ldc + col] =
                make_float2(acc[mt][nt][2], acc[mt][nt][3]);
        }
    }
}

// ---------------- RMSNorm + partial RoPE -> fp16 scatter -------------------
__global__ __launch_bounds__(256) void norm_rope(
    const float* __restrict__ qn, const float* __restrict__ kn,
    const int* __restrict__ pos_ids)
{
    int m = blockIdx.x;
    int b = m / Ss, s = m % Ss;
    int warp = threadIdx.x >> 5, lane = threadIdx.x & 31;
    float pos = (float)pos_ids[s];

    for (int iv = warp; iv < 48; iv += 8) {
        const float* src = g_qkv + (size_t)m * NTOT + iv * 64;
        float x1 = src[lane], x2 = src[lane + 32];
        if (iv < 40) {
            float ssum = x1 * x1 + x2 * x2;
#pragma unroll
            for (int o = 16; o >= 1; o >>= 1)
                ssum += __shfl_xor_sync(0xffffffffu, ssum, o);
            float inv = rsqrtf(ssum * (1.f / 64.f) + 1e-5f);
            const float* w = (iv < 32) ? qn : kn;
            x1 = x1 * inv * w[lane];
            x2 = x2 * inv * w[lane + 32];
            float invf = (lane < 16) ? exp2f(-0.625f * (float)lane) : 0.f;
            float f = pos * invf;
            float sn = sinf(f), cs = cosf(f);
            float o1 = x1 * cs - x2 * sn;
            float o2 = x2 * cs + x1 * sn;
            x1 = o1; x2 = o2;
        }
        unsigned short h1, l1, h2, l2;
        splith(x1, h1, l1); splith(x2, h2, l2);
        if (iv < 32) {
            size_t base = ((size_t)(b * 32 + iv) * Ss + s) * HD;
            g_qh[base + lane] = h1;
            g_qh[base + lane + 32] = h2;
        } else if (iv < 40) {
            size_t base = ((size_t)(b * KVH + (iv - 32)) * Ss + s) * HD;
            g_kh[base + lane] = h1;      g_kl[base + lane] = l1;
            g_kh[base + lane + 32] = h2; g_kl[base + lane + 32] = l2;
        } else {
            size_t base = (size_t)(b * KVH + (iv - 40)) * HD * Ss;
            g_vth[base + (size_t)lane * Ss + s] = h1;
            g_vtl[base + (size_t)lane * Ss + s] = l1;
            g_vth[base + (size_t)(lane + 32) * Ss + s] = h2;
            g_vtl[base + (size_t)(lane + 32) * Ss + s] = l2;
        }
    }
}

// ---------------- MMA flash attention (fp16 2-term) ------------------------
#define QT (128*72)
#define KT (64*72)
#define AST (4*KT)                    // KH, KL, VH, VL
#define ATT_SMEM ((QT + 2*AST)*2)     // 92160 bytes

__global__ __launch_bounds__(256, 1) void attn_mma()
{
    extern __shared__ unsigned short sm[];
    const int tid = threadIdx.x, lane = tid & 31, wm = tid >> 5;
    const int g = lane >> 2, t = lane & 3;
    const int head = blockIdx.x;
    const int qb = 15 - (int)blockIdx.y;
    const int b = head >> 5, gp = head & 31, kvg = gp >> 2;
    const int rb = qb * 128 + wm * 16;

    const unsigned short* Qh = g_qh + ((size_t)head * Ss + qb * 128) * HD;
    const unsigned short* Kh = g_kh + (size_t)(b * KVH + kvg) * Ss * HD;
    const unsigned short* Kl = g_kl + (size_t)(b * KVH + kvg) * Ss * HD;
    const unsigned short* Vth = g_vth + (size_t)(b * KVH + kvg) * HD * Ss;
    const unsigned short* Vtl = g_vtl + (size_t)(b * KVH + kvg) * HD * Ss;

    unsigned short* QH = sm;

    {   // prefetch Q (hi only): 128 rows x 8 chunks = 1024 cp16, 4/thread
        int row = tid >> 1, cbq = (tid & 1) * 4;
#pragma unroll
        for (int c = cbq; c < cbq + 4; c++) {
            uint32_t so = row * 72 + c * 8;
            cp16(s2u(QH + so), Qh + row * 64 + c * 8);
        }
        asm volatile("cp.async.commit_group;" ::: "memory");
    }

    auto prefetchKV = [&](int kt){
        unsigned short* st = sm + QT + (kt & 1) * AST;
        int row = tid >> 2, cb2 = (tid & 3) * 2;
#pragma unroll
        for (int c = cb2; c < cb2 + 2; c++) {
            uint32_t so = row * 72 + c * 8;
            size_t ofk = (size_t)(kt * 64 + row) * HD + c * 8;
            size_t ofv = (size_t)row * Ss + kt * 64 + c * 8;
            cp16(s2u(st +        so), Kh  + ofk);
            cp16(s2u(st +   KT + so), Kl  + ofk);
            cp16(s2u(st + 2*KT + so), Vth + ofv);
            cp16(s2u(st + 3*KT + so), Vtl + ofv);
        }
        asm volatile("cp.async.commit_group;" ::: "memory");
    };

    prefetchKV(0);

    const int ktmax = 2 * qb + 1;
    float m0 = -1e30f, m1 = -1e30f, l0 = 0.f, l1 = 0.f;
    float oac[8][4];
#pragma unroll
    for (int nt = 0; nt < 8; nt++)
#pragma unroll
        for (int r = 0; r < 4; r++) oac[nt][r] = 0.f;
    uint32_t qfh[4][4];

    const int n_row = ((lane>>4)&1)*8 + (lane&7);
    const int n_kof = ((lane>>3)&1)*8;

    for (int kt = 0; kt <= ktmax; kt++) {
        if (kt < ktmax) {
            prefetchKV(kt + 1);
            asm volatile("cp.async.wait_group 1;" ::: "memory");
        } else {
            asm volatile("cp.async.wait_group 0;" ::: "memory");
        }
        __syncthreads();

        if (kt == 0) {
            const int qa_row = wm*16 + ((lane>>3)&1)*8 + (lane&7);
            const int qa_kof = (lane>>4)*8;
#pragma unroll
            for (int ks = 0; ks < 4; ks++)
                ldm4(qfh[ks], s2u(QH + qa_row * 72 + ks*16 + qa_kof));
        }

        if (kt * 64 <= rb + 15) {
            const unsigned short* KH = sm + QT + (kt & 1) * AST;
            const unsigned short* KL = KH + KT;
            const unsigned short* VH = KH + 2*KT;
            const unsigned short* VL = KH + 3*KT;

            // ---- S = Qh (Kh+Kl)^T (2-term) ----
            float sc[8][4];
#pragma unroll
            for (int nt = 0; nt < 8; nt++)
#pragma unroll
                for (int r = 0; r < 4; r++) sc[nt][r] = 0.f;
#pragma unroll
            for (int ks = 0; ks < 4; ks++) {
                uint32_t bh[16], bl[16];
#pragma unroll
                for (int np = 0; np < 4; np++) {
                    uint32_t so = (np*16 + n_row) * 72 + ks*16 + n_kof;
                    ldm4(&bh[np*4], s2u(KH + so));
                    ldm4(&bl[np*4], s2u(KL + so));
                }
#pragma unroll
                for (int nt = 0; nt < 8; nt++) {
                    mma16816(sc[nt], qfh[ks], &bh[nt*2]);
                    mma16816(sc[nt], qfh[ks], &bl[nt*2]);
                }
            }

            // ---- softcap + causal mask ----
            const bool needmask = (kt * 64 + 63 > rb);
#pragma unroll
            for (int nt = 0; nt < 8; nt++) {
#pragma unroll
                for (int r = 0; r < 4; r++) {
                    float d = sc[nt][r];
                    float z = d * 0.0025f, z2 = z * z;
                    float pq = 1.f + z2*(-0.33333334f + z2*(0.13333334f - z2*0.05396825f));
                    float v = d * 0.125f * pq;
                    if (needmask) {
                        int col = kt*64 + nt*8 + (t<<1) + (r & 1);
                        int row = rb + g + ((r >> 1) << 3);
                        if (col > row) v = -1e30f;
                    }
                    sc[nt][r] = v;
                }
            }

            // ---- online softmax ----
            float tm0 = -1e30f, tm1 = -1e30f;
#pragma unroll
            for (int nt = 0; nt < 8; nt++) {
                tm0 = fmaxf(tm0, fmaxf(sc[nt][0], sc[nt][1]));
                tm1 = fmaxf(tm1, fmaxf(sc[nt][2], sc[nt][3]));
            }
            tm0 = fmaxf(tm0, __shfl_xor_sync(0xffffffffu, tm0, 1));
            tm0 = fmaxf(tm0, __shfl_xor_sync(0xffffffffu, tm0, 2));
            tm1 = fmaxf(tm1, __shfl_xor_sync(0xffffffffu, tm1, 1));
            tm1 = fmaxf(tm1, __shfl_xor_sync(0xffffffffu, tm1, 2));
            float nm0 = fmaxf(m0, tm0), nm1 = fmaxf(m1, tm1);
            float a0 = __expf(m0 - nm0), a1 = __expf(m1 - nm1);
            m0 = nm0; m1 = nm1;
            float rs0 = 0.f, rs1 = 0.f;
#pragma unroll
            for (int nt = 0; nt < 8; nt++) {
                sc[nt][0] = __expf(sc[nt][0] - nm0);
                sc[nt][1] = __expf(sc[nt][1] - nm0);
                sc[nt][2] = __expf(sc[nt][2] - nm1);
                sc[nt][3] = __expf(sc[nt][3] - nm1);
                rs0 += sc[nt][0] + sc[nt][1];
                rs1 += sc[nt][2] + sc[nt][3];
            }
            rs0 += __shfl_xor_sync(0xffffffffu, rs0, 1);
            rs0 += __shfl_xor_sync(0xffffffffu, rs0, 2);
            rs1 += __shfl_xor_sync(0xffffffffu, rs1, 1);
            rs1 += __shfl_xor_sync(0xffffffffu, rs1, 2);
            l0 = l0 * a0 + rs0;
            l1 = l1 * a1 + rs1;
#pragma unroll
            for (int nt = 0; nt < 8; nt++) {
                oac[nt][0] *= a0; oac[nt][1] *= a0;
                oac[nt][2] *= a1; oac[nt][3] *= a1;
            }

            // ---- O += P (Vh+Vl) (2-term; P single fp16) ----
#pragma unroll
            for (int ks = 0; ks < 4; ks++) {
                uint32_t pha[4];
                pha[0] = packh(sc[2*ks][0],   sc[2*ks][1]);
                pha[1] = packh(sc[2*ks][2],   sc[2*ks][3]);
                pha[2] = packh(sc[2*ks+1][0], sc[2*ks+1][1]);
                pha[3] = packh(sc[2*ks+1][2], sc[2*ks+1][3]);
                uint32_t vh[16], vl[16];
#pragma unroll
                for (int np = 0; np < 4; np++) {
                    uint32_t so = (np*16 + n_row) * 72 + ks*16 + n_kof;
                    ldm4(&vh[np*4], s2u(VH + so));
                    ldm4(&vl[np*4], s2u(VL + so));
                }
#pragma unroll
                for (int nt = 0; nt < 8; nt++) {
                    mma16816(oac[nt], pha, &vh[nt*2]);
                    mma16816(oac[nt], pha, &vl[nt*2]);
                }
            }
        }
        __syncthreads();
    }

    // ---- epilogue: normalize, store fp16 ----
    float i0 = 1.f / l0, i1 = 1.f / l1;
    size_t r0 = ((size_t)b * Ss + rb + g) * 2048;
    size_t r1 = ((size_t)b * Ss + rb + 8 + g) * 2048;
#pragma unroll
    for (int nt = 0; nt < 8; nt++) {
        int col = gp * 64 + nt * 8 + t * 2;
        *(uint32_t*)&g_af[r0 + col] = packh(oac[nt][0] * i0, oac[nt][1] * i0);
        *(uint32_t*)&g_af[r1 + col] = packh(oac[nt][2] * i1, oac[nt][3] * i1);
    }
}

// ---------------- launch ---------------------------------------------------
extern "C" void kernel_launch(void* const* d_in, const int* in_sizes, int n_in,
                              void* d_out, int out_size)
{
    const float* x  = (const float*)d_in[0];
    const float* wq = (const float*)d_in[1];
    const float* wk = (const float*)d_in[2];
    const float* wv = (const float*)d_in[3];
    const float* wo = (const float*)d_in[4];
    const float* qn = (const float*)d_in[5];
    const float* kn = (const float*)d_in[6];
    const int* pos  = (const int*)d_in[7];
    float* out = (float*)d_out;

    float* qkv;
    cudaGetSymbolAddress((void**)&qkv, g_qkv);
    unsigned short *xh, *wh, *wl, *oh, *ol, *af;
    cudaGetSymbolAddress((void**)&xh, g_xh);
    cudaGetSymbolAddress((void**)&wh, g_wh);  cudaGetSymbolAddress((void**)&wl, g_wl);
    cudaGetSymbolAddress((void**)&oh, g_oh);  cudaGetSymbolAddress((void**)&ol, g_ol);
    cudaGetSymbolAddress((void**)&af, g_af);

    cudaFuncSetAttribute(gemm_mma, cudaFuncAttributeMaxDynamicSharedMemorySize, GEMM_SMEM);
    cudaFuncSetAttribute(attn_mma, cudaFuncAttributeMaxDynamicSharedMemorySize, ATT_SMEM);

    tohalf <<<8192, 256>>>((const float4*)x,  (uint2*)xh, 2097152);
    split16<<<4096, 256>>>((const float4*)wq, (uint2*)wh, (uint2*)wl, 1048576);
    split16<<<1024, 256>>>((const float4*)wk, (uint2*)(wh + 4194304), (uint2*)(wl + 4194304), 262144);
    split16<<<1024, 256>>>((const float4*)wv, (uint2*)(wh + 5242880), (uint2*)(wl + 5242880), 262144);
    split16<<<4096, 256>>>((const float4*)wo, (uint2*)oh, (uint2*)ol, 1048576);

    gemm_mma<<<dim3(24, 32), 512, GEMM_SMEM>>>(xh, wh, wl, qkv, Dd, NTOT);
    norm_rope<<<Mtot, 256>>>(qn, kn, pos);
    attn_mma<<<dim3(64, 16), 256, ATT_SMEM>>>();
    gemm_mma<<<dim3(16, 32), 512, GEMM_SMEM>>>(af, oh, ol, out, Dd, Dd);
}

// round 8
// speedup vs baseline: 5.4253x; 1.4900x over previous
#include <cuda_runtime.h>
#include <cuda_fp16.h>
#include <cstdint>

#define Bb 2
#define Ss 2048
#define Dd 2048
#define KVH 8
#define QPG 4
#define HD 64
#define Mtot (Bb*Ss)            // 4096
#define NQ (KVH*QPG*HD)         // 2048
#define NKV (KVH*HD)            // 512
#define NTOT (NQ + 2*NKV)       // 3072

// ---------------- scratch (module-load static, no runtime allocs) ----------
__device__ float g_qkv[(size_t)Mtot * NTOT];

__device__ unsigned short g_xh[(size_t)Mtot*Dd];                 // x fp16
__device__ unsigned short g_wh[(size_t)NTOT*Dd];                 // wq|wk|wv fp16
__device__ unsigned short g_oh[(size_t)Dd*NQ];                   // wo fp16
__device__ unsigned short g_af[(size_t)Mtot*NQ];                 // attn out fp16
__device__ unsigned short g_qh[(size_t)64*Ss*HD];                // [head][s][h]
__device__ unsigned short g_kh[(size_t)16*Ss*HD];                // [bg][s][h]
__device__ unsigned short g_vth[(size_t)16*HD*Ss];               // [bg][h][s]

// ---------------- helpers ---------------------------------------------------
__device__ __forceinline__ uint32_t s2u(const void* p){
    uint32_t a;
    asm("{ .reg .u64 t; cvta.to.shared.u64 t, %1; cvt.u32.u64 %0, t; }":"=r"(a):"l"(p));
    return a;
}
__device__ __forceinline__ void cp16(uint32_t d, const void* g){
    asm volatile("cp.async.cg.shared.global [%0], [%1], 16;" :: "r"(d), "l"(g));
}
__device__ __forceinline__ void ldm4(uint32_t* r, uint32_t addr){
    asm volatile("ldmatrix.sync.aligned.m8n8.x4.shared.b16 {%0,%1,%2,%3}, [%4];"
        : "=r"(r[0]), "=r"(r[1]), "=r"(r[2]), "=r"(r[3]) : "r"(addr));
}
__device__ __forceinline__ void mma16816(float* c, const uint32_t* a, const uint32_t* b){
    asm volatile("mma.sync.aligned.m16n8k16.row.col.f32.f16.f16.f32 "
        "{%0,%1,%2,%3}, {%4,%5,%6,%7}, {%8,%9}, {%0,%1,%2,%3};"
        : "+f"(c[0]), "+f"(c[1]), "+f"(c[2]), "+f"(c[3])
        : "r"(a[0]), "r"(a[1]), "r"(a[2]), "r"(a[3]), "r"(b[0]), "r"(b[1]));
}
__device__ __forceinline__ uint32_t packh(float lo, float hi){
    uint32_t r;
    asm("cvt.rn.f16x2.f32 %0, %1, %2;" : "=r"(r) : "f"(hi), "f"(lo));
    return r;
}

// ---------------- fp32 -> fp16 convert -------------------------------------
__global__ __launch_bounds__(256) void tohalf(const float4* __restrict__ s,
        uint2* __restrict__ hi, int n4)
{
    int i = blockIdx.x*blockDim.x + threadIdx.x;
    if (i >= n4) return;
    float4 v = s[i];
    hi[i] = make_uint2(packh(v.x, v.y), packh(v.z, v.w));
}

// ---------------- HMMA GEMM: C = A @ B^T, fp16, fp32 acc -------------------
#define T_ELEMS (128*40)
#define STG_ELEMS (2*T_ELEMS)
#define GEMM_SMEM (3*STG_ELEMS*2)   // 61440 bytes

__global__ __launch_bounds__(512, 1) void gemm_mma(
    const unsigned short* __restrict__ A,
    const unsigned short* __restrict__ B,
    float* __restrict__ C, int Kd, int ldc)
{
    extern __shared__ unsigned short sm[];
    const int tid = threadIdx.x, lane = tid & 31, wid = tid >> 5;
    const int wm = wid >> 2, wn = wid & 3;      // 4 x 4 warp grid, 32x32 per warp
    const int g = lane >> 2, t = lane & 3;
    const int Mb = blockIdx.y * 128, Nb = blockIdx.x * 128;
    const int NC = Kd >> 5;

    float acc[2][4][4];
#pragma unroll
    for (int mt = 0; mt < 2; mt++)
#pragma unroll
        for (int nt = 0; nt < 4; nt++)
#pragma unroll
            for (int r = 0; r < 4; r++) acc[mt][nt][r] = 0.f;

    const int lrow = tid >> 2;
    const int lch  = tid & 3;

    auto prefetch = [&](int c){
        unsigned short* s = sm + (c % 3) * STG_ELEMS;
        const int k0 = c << 5;
        uint32_t so = lrow * 40 + lch * 8;
        cp16(s2u(s + so),           A + (size_t)(Mb + lrow) * Kd + k0 + lch * 8);
        cp16(s2u(s + T_ELEMS + so), B + (size_t)(Nb + lrow) * Kd + k0 + lch * 8);
        asm volatile("cp.async.commit_group;" ::: "memory");
    };

    const int a_row = wm*32 + ((lane>>3)&1)*8 + (lane&7);
    const int a_kof = (lane>>4)*8;
    const int b_row = wn*32 + ((lane>>4)&1)*8 + (lane&7);
    const int b_kof = ((lane>>3)&1)*8;

    prefetch(0);
    prefetch(1);
    for (int c = 0; c < NC; c++) {
        if (c + 1 < NC) { asm volatile("cp.async.wait_group 1;" ::: "memory"); }
        else            { asm volatile("cp.async.wait_group 0;" ::: "memory"); }
        __syncthreads();
        if (c + 2 < NC) prefetch(c + 2);

        const unsigned short* s = sm + (c % 3) * STG_ELEMS;
#pragma unroll
        for (int kk = 0; kk < 2; kk++) {
            const int ak = kk*16 + a_kof, bk = kk*16 + b_kof;
            uint32_t ah[2][4], bh[8];
#pragma unroll
            for (int mt = 0; mt < 2; mt++)
                ldm4(ah[mt], s2u(s + (a_row + mt*16) * 40 + ak));
#pragma unroll
            for (int np = 0; np < 2; np++)
                ldm4(&bh[np*4], s2u(s + T_ELEMS + (b_row + np*16) * 40 + bk));
#pragma unroll
            for (int mt = 0; mt < 2; mt++)
#pragma unroll
                for (int nt = 0; nt < 4; nt++)
                    mma16816(acc[mt][nt], ah[mt], &bh[nt*2]);
        }
    }

#pragma unroll
    for (int mt = 0; mt < 2; mt++) {
        int row = Mb + wm*32 + mt*16 + g;
#pragma unroll
        for (int nt = 0; nt < 4; nt++) {
            int col = Nb + wn*32 + nt*8 + t*2;
            *(float2*)&C[(size_t)row * ldc + col] =
                make_float2(acc[mt][nt][0], acc[mt][nt][1]);
            *(float2*)&C[(size_t)(row + 8) * ldc + col] =
                make_float2(acc[mt][nt][2], acc[mt][nt][3]);
        }
    }
}

// ---------------- RMSNorm + partial RoPE -> fp16 scatter -------------------
__global__ __launch_bounds__(256) void norm_rope(
    const float* __restrict__ qn, const float* __restrict__ kn,
    const int* __restrict__ pos_ids)
{
    int m = blockIdx.x;
    int b = m / Ss, s = m % Ss;
    int warp = threadIdx.x >> 5, lane = threadIdx.x & 31;
    float pos = (float)pos_ids[s];

    for (int iv = warp; iv < 48; iv += 8) {
        const float* src = g_qkv + (size_t)m * NTOT + iv * 64;
        float x1 = src[lane], x2 = src[lane + 32];
        if (iv < 40) {
            float ssum = x1 * x1 + x2 * x2;
#pragma unroll
            for (int o = 16; o >= 1; o >>= 1)
                ssum += __shfl_xor_sync(0xffffffffu, ssum, o);
            float inv = rsqrtf(ssum * (1.f / 64.f) + 1e-5f);
            const float* w = (iv < 32) ? qn : kn;
            x1 = x1 * inv * w[lane];
            x2 = x2 * inv * w[lane + 32];
            float invf = (lane < 16) ? exp2f(-0.625f * (float)lane) : 0.f;
            float f = pos * invf;
            float sn = sinf(f), cs = cosf(f);
            float o1 = x1 * cs - x2 * sn;
            float o2 = x2 * cs + x1 * sn;
            x1 = o1; x2 = o2;
        }
        __half h1 = __float2half(x1), h2 = __float2half(x2);
        unsigned short u1 = *(unsigned short*)&h1, u2 = *(unsigned short*)&h2;
        if (iv < 32) {
            size_t base = ((size_t)(b * 32 + iv) * Ss + s) * HD;
            g_qh[base + lane] = u1;
            g_qh[base + lane + 32] = u2;
        } else if (iv < 40) {
            size_t base = ((size_t)(b * KVH + (iv - 32)) * Ss + s) * HD;
            g_kh[base + lane] = u1;
            g_kh[base + lane + 32] = u2;
        } else {
            size_t base = (size_t)(b * KVH + (iv - 40)) * HD * Ss;
            g_vth[base + (size_t)lane * Ss + s] = u1;
            g_vth[base + (size_t)(lane + 32) * Ss + s] = u2;
        }
    }
}

// ---------------- MMA flash attention (fp16 1-term) ------------------------
#define QT (128*72)
#define KT (64*72)
#define AST (2*KT)                    // KH, VH
#define ATT_SMEM ((QT + 2*AST)*2)     // 55296 bytes

__global__ __launch_bounds__(256, 1) void attn_mma()
{
    extern __shared__ unsigned short sm[];
    const int tid = threadIdx.x, lane = tid & 31, wm = tid >> 5;
    const int g = lane >> 2, t = lane & 3;
    const int head = blockIdx.x;
    const int qb = 15 - (int)blockIdx.y;
    const int b = head >> 5, gp = head & 31, kvg = gp >> 2;
    const int rb = qb * 128 + wm * 16;

    const unsigned short* Qh = g_qh + ((size_t)head * Ss + qb * 128) * HD;
    const unsigned short* Kh = g_kh + (size_t)(b * KVH + kvg) * Ss * HD;
    const unsigned short* Vth = g_vth + (size_t)(b * KVH + kvg) * HD * Ss;

    unsigned short* QH = sm;

    {   // prefetch Q
        int row = tid >> 1, cbq = (tid & 1) * 4;
#pragma unroll
        for (int c = cbq; c < cbq + 4; c++) {
            uint32_t so = row * 72 + c * 8;
            cp16(s2u(QH + so), Qh + row * 64 + c * 8);
        }
        asm volatile("cp.async.commit_group;" ::: "memory");
    }

    auto prefetchKV = [&](int kt){
        unsigned short* st = sm + QT + (kt & 1) * AST;
        int row = tid >> 2, cb2 = (tid & 3) * 2;
#pragma unroll
        for (int c = cb2; c < cb2 + 2; c++) {
            uint32_t so = row * 72 + c * 8;
            cp16(s2u(st +      so), Kh  + (size_t)(kt * 64 + row) * HD + c * 8);
            cp16(s2u(st + KT + so), Vth + (size_t)row * Ss + kt * 64 + c * 8);
        }
        asm volatile("cp.async.commit_group;" ::: "memory");
    };

    prefetchKV(0);

    const int ktmax = 2 * qb + 1;
    float m0 = -1e30f, m1 = -1e30f, l0 = 0.f, l1 = 0.f;
    float oac[8][4];
#pragma unroll
    for (int nt = 0; nt < 8; nt++)
#pragma unroll
        for (int r = 0; r < 4; r++) oac[nt][r] = 0.f;
    uint32_t qfh[4][4];

    const int n_row = ((lane>>4)&1)*8 + (lane&7);
    const int n_kof = ((lane>>3)&1)*8;

    for (int kt = 0; kt <= ktmax; kt++) {
        if (kt < ktmax) {
            prefetchKV(kt + 1);
            asm volatile("cp.async.wait_group 1;" ::: "memory");
        } else {
            asm volatile("cp.async.wait_group 0;" ::: "memory");
        }
        __syncthreads();

        if (kt == 0) {
            const int qa_row = wm*16 + ((lane>>3)&1)*8 + (lane&7);
            const int qa_kof = (lane>>4)*8;
#pragma unroll
            for (int ks = 0; ks < 4; ks++)
                ldm4(qfh[ks], s2u(QH + qa_row * 72 + ks*16 + qa_kof));
        }

        if (kt * 64 <= rb + 15) {
            const unsigned short* KH = sm + QT + (kt & 1) * AST;
            const unsigned short* VH = KH + KT;

            // ---- S = Q K^T ----
            float sc[8][4];
#pragma unroll
            for (int nt = 0; nt < 8; nt++)
#pragma unroll
                for (int r = 0; r < 4; r++) sc[nt][r] = 0.f;
#pragma unroll
            for (int ks = 0; ks < 4; ks++) {
                uint32_t bh[16];
#pragma unroll
                for (int np = 0; np < 4; np++)
                    ldm4(&bh[np*4], s2u(KH + (np*16 + n_row) * 72 + ks*16 + n_kof));
#pragma unroll
                for (int nt = 0; nt < 8; nt++)
                    mma16816(sc[nt], qfh[ks], &bh[nt*2]);
            }

            // ---- softcap + causal mask ----
            const bool needmask = (kt * 64 + 63 > rb);
#pragma unroll
            for (int nt = 0; nt < 8; nt++) {
#pragma unroll
                for (int r = 0; r < 4; r++) {
                    float d = sc[nt][r];
                    float z = d * 0.0025f, z2 = z * z;
                    float pq = 1.f + z2*(-0.33333334f + z2*(0.13333334f - z2*0.05396825f));
                    float v = d * 0.125f * pq;
                    if (needmask) {
                        int col = kt*64 + nt*8 + (t<<1) + (r & 1);
                        int row = rb + g + ((r >> 1) << 3);
                        if (col > row) v = -1e30f;
                    }
                    sc[nt][r] = v;
                }
            }

            // ---- online softmax ----
            float tm0 = -1e30f, tm1 = -1e30f;
#pragma unroll
            for (int nt = 0; nt < 8; nt++) {
                tm0 = fmaxf(tm0, fmaxf(sc[nt][0], sc[nt][1]));
                tm1 = fmaxf(tm1, fmaxf(sc[nt][2], sc[nt][3]));
            }
            tm0 = fmaxf(tm0, __shfl_xor_sync(0xffffffffu, tm0, 1));
            tm0 = fmaxf(tm0, __shfl_xor_sync(0xffffffffu, tm0, 2));
            tm1 = fmaxf(tm1, __shfl_xor_sync(0xffffffffu, tm1, 1));
            tm1 = fmaxf(tm1, __shfl_xor_sync(0xffffffffu, tm1, 2));
            float nm0 = fmaxf(m0, tm0), nm1 = fmaxf(m1, tm1);
            float a0 = __expf(m0 - nm0), a1 = __expf(m1 - nm1);
            m0 = nm0; m1 = nm1;
            float rs0 = 0.f, rs1 = 0.f;
#pragma unroll
            for (int nt = 0; nt < 8; nt++) {
                sc[nt][0] = __expf(sc[nt][0] - nm0);
                sc[nt][1] = __expf(sc[nt][1] - nm0);
                sc[nt][2] = __expf(sc[nt][2] - nm1);
                sc[nt][3] = __expf(sc[nt][3] - nm1);
                rs0 += sc[nt][0] + sc[nt][1];
                rs1 += sc[nt][2] + sc[nt][3];
            }
            rs0 += __shfl_xor_sync(0xffffffffu, rs0, 1);
            rs0 += __shfl_xor_sync(0xffffffffu, rs0, 2);
            rs1 += __shfl_xor_sync(0xffffffffu, rs1, 1);
            rs1 += __shfl_xor_sync(0xffffffffu, rs1, 2);
            l0 = l0 * a0 + rs0;
            l1 = l1 * a1 + rs1;
#pragma unroll
            for (int nt = 0; nt < 8; nt++) {
                oac[nt][0] *= a0; oac[nt][1] *= a0;
                oac[nt][2] *= a1; oac[nt][3] *= a1;
            }

            // ---- O += P V ----
#pragma unroll
            for (int ks = 0; ks < 4; ks++) {
                uint32_t pha[4];
                pha[0] = packh(sc[2*ks][0],   sc[2*ks][1]);
                pha[1] = packh(sc[2*ks][2],   sc[2*ks][3]);
                pha[2] = packh(sc[2*ks+1][0], sc[2*ks+1][1]);
                pha[3] = packh(sc[2*ks+1][2], sc[2*ks+1][3]);
                uint32_t vh[16];
#pragma unroll
                for (int np = 0; np < 4; np++)
                    ldm4(&vh[np*4], s2u(VH + (np*16 + n_row) * 72 + ks*16 + n_kof));
#pragma unroll
                for (int nt = 0; nt < 8; nt++)
                    mma16816(oac[nt], pha, &vh[nt*2]);
            }
        }
        __syncthreads();
    }

    // ---- epilogue: normalize, store fp16 ----
    float i0 = 1.f / l0, i1 = 1.f / l1;
    size_t r0 = ((size_t)b * Ss + rb + g) * 2048;
    size_t r1 = ((size_t)b * Ss + rb + 8 + g) * 2048;
#pragma unroll
    for (int nt = 0; nt < 8; nt++) {
        int col = gp * 64 + nt * 8 + t * 2;
        *(uint32_t*)&g_af[r0 + col] = packh(oac[nt][0] * i0, oac[nt][1] * i0);
        *(uint32_t*)&g_af[r1 + col] = packh(oac[nt][2] * i1, oac[nt][3] * i1);
    }
}

// ---------------- launch ---------------------------------------------------
extern "C" void kernel_launch(void* const* d_in, const int* in_sizes, int n_in,
                              void* d_out, int out_size)
{
    const float* x  = (const float*)d_in[0];
    const float* wq = (const float*)d_in[1];
    const float* wk = (const float*)d_in[2];
    const float* wv = (const float*)d_in[3];
    const float* wo = (const float*)d_in[4];
    const float* qn = (const float*)d_in[5];
    const float* kn = (const float*)d_in[6];
    const int* pos  = (const int*)d_in[7];
    float* out = (float*)d_out;

    float* qkv;
    cudaGetSymbolAddress((void**)&qkv, g_qkv);
    unsigned short *xh, *wh, *oh, *af;
    cudaGetSymbolAddress((void**)&xh, g_xh);
    cudaGetSymbolAddress((void**)&wh, g_wh);
    cudaGetSymbolAddress((void**)&oh, g_oh);
    cudaGetSymbolAddress((void**)&af, g_af);

    cudaFuncSetAttribute(gemm_mma, cudaFuncAttributeMaxDynamicSharedMemorySize, GEMM_SMEM);
    cudaFuncSetAttribute(attn_mma, cudaFuncAttributeMaxDynamicSharedMemorySize, ATT_SMEM);

    tohalf<<<8192, 256>>>((const float4*)x,  (uint2*)xh, 2097152);
    tohalf<<<4096, 256>>>((const float4*)wq, (uint2*)wh, 1048576);
    tohalf<<<1024, 256>>>((const float4*)wk, (uint2*)(wh + 4194304), 262144);
    tohalf<<<1024, 256>>>((const float4*)wv, (uint2*)(wh + 5242880), 262144);
    tohalf<<<4096, 256>>>((const float4*)wo, (uint2*)oh, 1048576);

    gemm_mma<<<dim3(24, 32), 512, GEMM_SMEM>>>(xh, wh, qkv, Dd, NTOT);
    norm_rope<<<Mtot, 256>>>(qn, kn, pos);
    attn_mma<<<dim3(64, 16), 256, ATT_SMEM>>>();
    gemm_mma<<<dim3(16, 32), 512, GEMM_SMEM>>>(af, oh, out, Dd, Dd);
}

// round 10
// speedup vs baseline: 5.6860x; 1.0480x over previous
#include <cuda_runtime.h>
#include <cuda_fp16.h>
#include <cstdint>

#define Bb 2
#define Ss 2048
#define Dd 2048
#define KVH 8
#define QPG 4
#define HD 64
#define Mtot (Bb*Ss)            // 4096
#define NQ (KVH*QPG*HD)         // 2048
#define NKV (KVH*HD)            // 512
#define NTOT (NQ + 2*NKV)       // 3072

// ---------------- scratch (module-load static, no runtime allocs) ----------
__device__ __align__(16) unsigned short g_xh[(size_t)Mtot*Dd];    // x fp16
__device__ __align__(16) unsigned short g_wh[(size_t)NTOT*Dd];    // wq|wk|wv fp16
__device__ __align__(16) unsigned short g_oh[(size_t)Dd*NQ];      // wo fp16
__device__ __align__(16) unsigned short g_af[(size_t)Mtot*NQ];    // attn out fp16
__device__ __align__(16) unsigned short g_qh[(size_t)64*Ss*HD];   // [head][s][h]
__device__ __align__(16) unsigned short g_kh[(size_t)16*Ss*HD];   // [bg][s][h]
__device__ __align__(16) unsigned short g_vth[(size_t)16*HD*Ss];  // [bg][h][s]

// ---------------- helpers ---------------------------------------------------
__device__ __forceinline__ uint32_t s2u(const void* p){
    uint32_t a;
    asm("{ .reg .u64 t; cvta.to.shared.u64 t, %1; cvt.u32.u64 %0, t; }":"=r"(a):"l"(p));
    return a;
}
__device__ __forceinline__ void cp16(uint32_t d, const void* g){
    asm volatile("cp.async.cg.shared.global [%0], [%1], 16;" :: "r"(d), "l"(g));
}
__device__ __forceinline__ void ldm4(uint32_t* r, uint32_t addr){
    asm volatile("ldmatrix.sync.aligned.m8n8.x4.shared.b16 {%0,%1,%2,%3}, [%4];"
        : "=r"(r[0]), "=r"(r[1]), "=r"(r[2]), "=r"(r[3]) : "r"(addr));
}
__device__ __forceinline__ void mma16816(float* c, const uint32_t* a, const uint32_t* b){
    asm volatile("mma.sync.aligned.m16n8k16.row.col.f32.f16.f16.f32 "
        "{%0,%1,%2,%3}, {%4,%5,%6,%7}, {%8,%9}, {%0,%1,%2,%3};"
        : "+f"(c[0]), "+f"(c[1]), "+f"(c[2]), "+f"(c[3])
        : "r"(a[0]), "r"(a[1]), "r"(a[2]), "r"(a[3]), "r"(b[0]), "r"(b[1]));
}
__device__ __forceinline__ uint32_t packh(float lo, float hi){
    uint32_t r;
    asm("cvt.rn.f16x2.f32 %0, %1, %2;" : "=r"(r) : "f"(hi), "f"(lo));
    return r;
}

// ---------------- one-shot fp32 -> fp16 convert of all 5 tensors -----------
__global__ __launch_bounds__(256) void convert_all(
    const float4* __restrict__ x,  const float4* __restrict__ wq,
    const float4* __restrict__ wk, const float4* __restrict__ wv,
    const float4* __restrict__ wo,
    uint2* __restrict__ xh, uint2* __restrict__ wh, uint2* __restrict__ oh)
{
    int i = blockIdx.x*blockDim.x + threadIdx.x;
    const float4* s; uint2* d; int off;
    if (i < 2097152)      { s = x;  d = xh;           off = i; }
    else if (i < 3145728) { s = wq; d = wh;           off = i - 2097152; }
    else if (i < 3407872) { s = wk; d = wh + 1048576; off = i - 3145728; }
    else if (i < 3670016) { s = wv; d = wh + 1310720; off = i - 3407872; }
    else if (i < 4718592) { s = wo; d = oh;           off = i - 3670016; }
    else return;
    float4 v = s[off];
    d[off] = make_uint2(packh(v.x, v.y), packh(v.z, v.w));
}

// ---------------- shared GEMM tile constants -------------------------------
#define T_ELEMS (128*40)
#define STG_ELEMS (2*T_ELEMS)
#define GEMM_SMEM (3*STG_ELEMS*2)   // 61440 bytes

// ---------------- QKV GEMM with fused norm+rope+scatter epilogue -----------
__global__ __launch_bounds__(512, 1) void qkv_mma(
    const unsigned short* __restrict__ A,
    const unsigned short* __restrict__ B,
    const float* __restrict__ qn, const float* __restrict__ kn,
    const int* __restrict__ pos_ids)
{
    extern __shared__ unsigned short sm[];
    const int tid = threadIdx.x, lane = tid & 31, wid = tid >> 5;
    const int wm = wid >> 2, wn = wid & 3;
    const int g = lane >> 2, t = lane & 3;
    const int nb = blockIdx.x, mb = blockIdx.y;
    const int Mb = mb * 128, Nb = nb * 128;
    const int NC = Dd >> 5;   // 64

    float acc[2][4][4];
#pragma unroll
    for (int mt = 0; mt < 2; mt++)
#pragma unroll
        for (int nt = 0; nt < 4; nt++)
#pragma unroll
            for (int r = 0; r < 4; r++) acc[mt][nt][r] = 0.f;

    const int lrow = tid >> 2, lch = tid & 3;

    auto prefetch = [&](int c){
        unsigned short* s = sm + (c % 3) * STG_ELEMS;
        const int k0 = c << 5;
        uint32_t so = lrow * 40 + lch * 8;
        cp16(s2u(s + so),           A + (size_t)(Mb + lrow) * Dd + k0 + lch * 8);
        cp16(s2u(s + T_ELEMS + so), B + (size_t)(Nb + lrow) * Dd + k0 + lch * 8);
        asm volatile("cp.async.commit_group;" ::: "memory");
    };

    const int a_row = wm*32 + ((lane>>3)&1)*8 + (lane&7);
    const int a_kof = (lane>>4)*8;
    const int b_row = wn*32 + ((lane>>4)&1)*8 + (lane&7);
    const int b_kof = ((lane>>3)&1)*8;

    prefetch(0);
    prefetch(1);
    for (int c = 0; c < NC; c++) {
        if (c + 1 < NC) { asm volatile("cp.async.wait_group 1;" ::: "memory"); }
        else            { asm volatile("cp.async.wait_group 0;" ::: "memory"); }
        __syncthreads();
        if (c + 2 < NC) prefetch(c + 2);

        const unsigned short* s = sm + (c % 3) * STG_ELEMS;
#pragma unroll
        for (int kk = 0; kk < 2; kk++) {
            const int ak = kk*16 + a_kof, bk = kk*16 + b_kof;
            uint32_t ah[2][4], bh[8];
#pragma unroll
            for (int mt = 0; mt < 2; mt++)
                ldm4(ah[mt], s2u(s + (a_row + mt*16) * 40 + ak));
#pragma unroll
            for (int np = 0; np < 2; np++)
                ldm4(&bh[np*4], s2u(s + T_ELEMS + (b_row + np*16) * 40 + bk));
#pragma unroll
            for (int mt = 0; mt < 2; mt++)
#pragma unroll
                for (int nt = 0; nt < 4; nt++)
                    mma16816(acc[mt][nt], ah[mt], &bh[nt*2]);
        }
    }

    // ---- fused epilogue: stage tile as fp16 in smem ----
    __syncthreads();
    unsigned short* st = sm;                  // [128][132]
#pragma unroll
    for (int mt = 0; mt < 2; mt++) {
        int row = wm*32 + mt*16 + g;
        int colb = wn*32 + t*2;
#pragma unroll
        for (int nt = 0; nt < 4; nt++) {
            *(uint32_t*)&st[(size_t)row    *132 + colb + nt*8] = packh(acc[mt][nt][0], acc[mt][nt][1]);
            *(uint32_t*)&st[(size_t)(row+8)*132 + colb + nt*8] = packh(acc[mt][nt][2], acc[mt][nt][3]);
        }
    }
    __syncthreads();

    if (tid < 256) {                          // 256 work units in both paths
        if (nb >= 20) {
            // ---- V tiles: transpose-convert to g_vth[bg][h][s] ----
            int c  = tid >> 1;                 // tile col 0..127
            int rh = (tid & 1) * 64;           // row half
            int vcol = nb*128 + c - 2560;      // 0..511
            int kvg = vcol >> 6, h = vcol & 63;
            int m0 = Mb + rh;
            int b = m0 >> 11, s0 = m0 & 2047;
            unsigned short* dst = g_vth + ((size_t)(b*KVH + kvg)*HD + h)*Ss + s0;
#pragma unroll
            for (int i0 = 0; i0 < 64; i0 += 8) {
                uint32_t p[4];
#pragma unroll
                for (int j = 0; j < 4; j++) {
                    unsigned short va = st[(size_t)(rh + i0 + 2*j    )*132 + c];
                    unsigned short vb = st[(size_t)(rh + i0 + 2*j + 1)*132 + c];
                    p[j] = (uint32_t)va | ((uint32_t)vb << 16);
                }
                *(uint4*)(dst + i0) = make_uint4(p[0], p[1], p[2], p[3]);
            }
        } else {
            // ---- Q/K tiles: per-thread row-head rmsnorm + rope ----
            int row = tid & 127, hd = (tid >> 7) & 1;
            int m = Mb + row, b = m >> 11, s = m & 2047;
            uint32_t v2[32];
#pragma unroll
            for (int j = 0; j < 32; j++)
                v2[j] = *(uint32_t*)&st[(size_t)row*132 + hd*64 + j*2];
            float ssum = 0.f;
#pragma unroll
            for (int j = 0; j < 32; j++) {
                float2 f = __half22float2(*(__half2*)&v2[j]);
                ssum += f.x*f.x + f.y*f.y;
            }
            float inv = rsqrtf(ssum * (1.f/64.f) + 1e-5f);
            const float* w = (nb < 16) ? qn : kn;
            float pos = (float)pos_ids[s];
            unsigned short* dst;
            if (nb < 16) {
                int qh = nb*2 + hd;
                dst = g_qh + ((size_t)(b*32 + qh)*Ss + s)*HD;
            } else {
                int kh = (nb - 16)*2 + hd;
                dst = g_kh + ((size_t)(b*KVH + kh)*Ss + s)*HD;
            }
            uint32_t outp[32];
#pragma unroll
            for (int j = 0; j < 16; j++) {
                float2 lo2 = __half22float2(*(__half2*)&v2[j]);      // dims 2j, 2j+1
                float2 hi2 = __half22float2(*(__half2*)&v2[j+16]);   // dims 2j+32, 2j+33
                float x1a = lo2.x * inv * w[2*j];
                float x1b = lo2.y * inv * w[2*j+1];
                float x2a = hi2.x * inv * w[2*j+32];
                float x2b = hi2.y * inv * w[2*j+33];
                float o1a = x1a, o1b = x1b, o2a = x2a, o2b = x2b;
                if (j < 8) {   // dims < 16 rotate
                    float fA = pos * exp2f(-0.625f * (float)(2*j));
                    float fB = pos * exp2f(-0.625f * (float)(2*j+1));
                    float snA = sinf(fA), csA = cosf(fA);
                    float snB = sinf(fB), csB = cosf(fB);
                    o1a = x1a*csA - x2a*snA;  o2a = x2a*csA + x1a*snA;
                    o1b = x1b*csB - x2b*snB;  o2b = x2b*csB + x1b*snB;
                }
                outp[j]      = packh(o1a, o1b);
                outp[j + 16] = packh(o2a, o2b);
            }
#pragma unroll
            for (int i0 = 0; i0 < 32; i0 += 4)
                *(uint4*)(dst + i0*2) = make_uint4(outp[i0], outp[i0+1], outp[i0+2], outp[i0+3]);
        }
    }
}

// ---------------- generic HMMA GEMM (out-projection) -----------------------
__global__ __launch_bounds__(512, 1) void gemm_mma(
    const unsigned short* __restrict__ A,
    const unsigned short* __restrict__ B,
    float* __restrict__ C, int Kd, int ldc)
{
    extern __shared__ unsigned short sm[];
    const int tid = threadIdx.x, lane = tid & 31, wid = tid >> 5;
    const int wm = wid >> 2, wn = wid & 3;
    const int g = lane >> 2, t = lane & 3;
    const int Mb = blockIdx.y * 128, Nb = blockIdx.x * 128;
    const int NC = Kd >> 5;

    float acc[2][4][4];
#pragma unroll
    for (int mt = 0; mt < 2; mt++)
#pragma unroll
        for (int nt = 0; nt < 4; nt++)
#pragma unroll
            for (int r = 0; r < 4; r++) acc[mt][nt][r] = 0.f;

    const int lrow = tid >> 2, lch = tid & 3;

    auto prefetch = [&](int c){
        unsigned short* s = sm + (c % 3) * STG_ELEMS;
        const int k0 = c << 5;
        uint32_t so = lrow * 40 + lch * 8;
        cp16(s2u(s + so),           A + (size_t)(Mb + lrow) * Kd + k0 + lch * 8);
        cp16(s2u(s + T_ELEMS + so), B + (size_t)(Nb + lrow) * Kd + k0 + lch * 8);
        asm volatile("cp.async.commit_group;" ::: "memory");
    };

    const int a_row = wm*32 + ((lane>>3)&1)*8 + (lane&7);
    const int a_kof = (lane>>4)*8;
    const int b_row = wn*32 + ((lane>>4)&1)*8 + (lane&7);
    const int b_kof = ((lane>>3)&1)*8;

    prefetch(0);
    prefetch(1);
    for (int c = 0; c < NC; c++) {
        if (c + 1 < NC) { asm volatile("cp.async.wait_group 1;" ::: "memory"); }
        else            { asm volatile("cp.async.wait_group 0;" ::: "memory"); }
        __syncthreads();
        if (c + 2 < NC) prefetch(c + 2);

        const unsigned short* s = sm + (c % 3) * STG_ELEMS;
#pragma unroll
        for (int kk = 0; kk < 2; kk++) {
            const int ak = kk*16 + a_kof, bk = kk*16 + b_kof;
            uint32_t ah[2][4], bh[8];
#pragma unroll
            for (int mt = 0; mt < 2; mt++)
                ldm4(ah[mt], s2u(s + (a_row + mt*16) * 40 + ak));
#pragma unroll
            for (int np = 0; np < 2; np++)
                ldm4(&bh[np*4], s2u(s + T_ELEMS + (b_row + np*16) * 40 + bk));
#pragma unroll
            for (int mt = 0; mt < 2; mt++)
#pragma unroll
                for (int nt = 0; nt < 4; nt++)
                    mma16816(acc[mt][nt], ah[mt], &bh[nt*2]);
        }
    }

#pragma unroll
    for (int mt = 0; mt < 2; mt++) {
        int row = Mb + wm*32 + mt*16 + g;
#pragma unroll
        for (int nt = 0; nt < 4; nt++) {
            int col = Nb + wn*32 + nt*8 + t*2;
            *(float2*)&C[(size_t)row * ldc + col] =
                make_float2(acc[mt][nt][0], acc[mt][nt][1]);
            *(float2*)&C[(size_t)(row + 8) * ldc + col] =
                make_float2(acc[mt][nt][2], acc[mt][nt][3]);
        }
    }
}

// ---------------- MMA flash attention (fp16 1-term) ------------------------
#define QT (128*72)
#define KT (64*72)
#define AST (2*KT)
#define ATT_SMEM ((QT + 2*AST)*2)

__global__ __launch_bounds__(256, 1) void attn_mma()
{
    extern __shared__ unsigned short sm[];
    const int tid = threadIdx.x, lane = tid & 31, wm = tid >> 5;
    const int g = lane >> 2, t = lane & 3;
    const int head = blockIdx.x;
    const int qb = 15 - (int)blockIdx.y;
    const int b = head >> 5, gp = head & 31, kvg = gp >> 2;
    const int rb = qb * 128 + wm * 16;

    const unsigned short* Qh = g_qh + ((size_t)head * Ss + qb * 128) * HD;
    const unsigned short* Kh = g_kh + (size_t)(b * KVH + kvg) * Ss * HD;
    const unsigned short* Vth = g_vth + (size_t)(b * KVH + kvg) * HD * Ss;

    unsigned short* QH = sm;

    {
        int row = tid >> 1, cbq = (tid & 1) * 4;
#pragma unroll
        for (int c = cbq; c < cbq + 4; c++) {
            uint32_t so = row * 72 + c * 8;
            cp16(s2u(QH + so), Qh + row * 64 + c * 8);
        }
        asm volatile("cp.async.commit_group;" ::: "memory");
    }

    auto prefetchKV = [&](int kt){
        unsigned short* st = sm + QT + (kt & 1) * AST;
        int row = tid >> 2, cb2 = (tid & 3) * 2;
#pragma unroll
        for (int c = cb2; c < cb2 + 2; c++) {
            uint32_t so = row * 72 + c * 8;
            cp16(s2u(st +      so), Kh  + (size_t)(kt * 64 + row) * HD + c * 8);
            cp16(s2u(st + KT + so), Vth + (size_t)row * Ss + kt * 64 + c * 8);
        }
        asm volatile("cp.async.commit_group;" ::: "memory");
    };

    prefetchKV(0);

    const int ktmax = 2 * qb + 1;
    float m0 = -1e30f, m1 = -1e30f, l0 = 0.f, l1 = 0.f;
    float oac[8][4];
#pragma unroll
    for (int nt = 0; nt < 8; nt++)
#pragma unroll
        for (int r = 0; r < 4; r++) oac[nt][r] = 0.f;
    uint32_t qfh[4][4];

    const int n_row = ((lane>>4)&1)*8 + (lane&7);
    const int n_kof = ((lane>>3)&1)*8;

    for (int kt = 0; kt <= ktmax; kt++) {
        if (kt < ktmax) {
            prefetchKV(kt + 1);
            asm volatile("cp.async.wait_group 1;" ::: "memory");
        } else {
            asm volatile("cp.async.wait_group 0;" ::: "memory");
        }
        __syncthreads();

        if (kt == 0) {
            const int qa_row = wm*16 + ((lane>>3)&1)*8 + (lane&7);
            const int qa_kof = (lane>>4)*8;
#pragma unroll
            for (int ks = 0; ks < 4; ks++)
                ldm4(qfh[ks], s2u(QH + qa_row * 72 + ks*16 + qa_kof));
        }

        if (kt * 64 <= rb + 15) {
            const unsigned short* KH = sm + QT + (kt & 1) * AST;
            const unsigned short* VH = KH + KT;

            float sc[8][4];
#pragma unroll
            for (int nt = 0; nt < 8; nt++)
#pragma unroll
                for (int r = 0; r < 4; r++) sc[nt][r] = 0.f;
#pragma unroll
            for (int ks = 0; ks < 4; ks++) {
                uint32_t bh[16];
#pragma unroll
                for (int np = 0; np < 4; np++)
                    ldm4(&bh[np*4], s2u(KH + (np*16 + n_row) * 72 + ks*16 + n_kof));
#pragma unroll
                for (int nt = 0; nt < 8; nt++)
                    mma16816(sc[nt], qfh[ks], &bh[nt*2]);
            }

            const bool needmask = (kt * 64 + 63 > rb);
#pragma unroll
            for (int nt = 0; nt < 8; nt++) {
#pragma unroll
                for (int r = 0; r < 4; r++) {
                    float d = sc[nt][r];
                    float z = d * 0.0025f, z2 = z * z;
                    float pq = 1.f + z2*(-0.33333334f + z2*(0.13333334f - z2*0.05396825f));
                    float v = d * 0.125f * pq;
                    if (needmask) {
                        int col = kt*64 + nt*8 + (t<<1) + (r & 1);
                        int row = rb + g + ((r >> 1) << 3);
                        if (col > row) v = -1e30f;
                    }
                    sc[nt][r] = v;
                }
            }

            float tm0 = -1e30f, tm1 = -1e30f;
#pragma unroll
            for (int nt = 0; nt < 8; nt++) {
                tm0 = fmaxf(tm0, fmaxf(sc[nt][0], sc[nt][1]));
                tm1 = fmaxf(tm1, fmaxf(sc[nt][2], sc[nt][3]));
            }
            tm0 = fmaxf(tm0, __shfl_xor_sync(0xffffffffu, tm0, 1));
            tm0 = fmaxf(tm0, __shfl_xor_sync(0xffffffffu, tm0, 2));
            tm1 = fmaxf(tm1, __shfl_xor_sync(0xffffffffu, tm1, 1));
            tm1 = fmaxf(tm1, __shfl_xor_sync(0xffffffffu, tm1, 2));
            float nm0 = fmaxf(m0, tm0), nm1 = fmaxf(m1, tm1);
            float a0 = __expf(m0 - nm0), a1 = __expf(m1 - nm1);
            m0 = nm0; m1 = nm1;
            float rs0 = 0.f, rs1 = 0.f;
#pragma unroll
            for (int nt = 0; nt < 8; nt++) {
                sc[nt][0] = __expf(sc[nt][0] - nm0);
                sc[nt][1] = __expf(sc[nt][1] - nm0);
                sc[nt][2] = __expf(sc[nt][2] - nm1);
                sc[nt][3] = __expf(sc[nt][3] - nm1);
                rs0 += sc[nt][0] + sc[nt][1];
                rs1 += sc[nt][2] + sc[nt][3];
            }
            rs0 += __shfl_xor_sync(0xffffffffu, rs0, 1);
            rs0 += __shfl_xor_sync(0xffffffffu, rs0, 2);
            rs1 += __shfl_xor_sync(0xffffffffu, rs1, 1);
            rs1 += __shfl_xor_sync(0xffffffffu, rs1, 2);
            l0 = l0 * a0 + rs0;
            l1 = l1 * a1 + rs1;
#pragma unroll
            for (int nt = 0; nt < 8; nt++) {
                oac[nt][0] *= a0; oac[nt][1] *= a0;
                oac[nt][2] *= a1; oac[nt][3] *= a1;
            }

#pragma unroll
            for (int ks = 0; ks < 4; ks++) {
                uint32_t pha[4];
                pha[0] = packh(sc[2*ks][0],   sc[2*ks][1]);
                pha[1] = packh(sc[2*ks][2],   sc[2*ks][3]);
                pha[2] = packh(sc[2*ks+1][0], sc[2*ks+1][1]);
                pha[3] = packh(sc[2*ks+1][2], sc[2*ks+1][3]);
                uint32_t vh[16];
#pragma unroll
                for (int np = 0; np < 4; np++)
                    ldm4(&vh[np*4], s2u(VH + (np*16 + n_row) * 72 + ks*16 + n_kof));
#pragma unroll
                for (int nt = 0; nt < 8; nt++)
                    mma16816(oac[nt], pha, &vh[nt*2]);
            }
        }
        __syncthreads();
    }

    float i0 = 1.f / l0, i1 = 1.f / l1;
    size_t r0 = ((size_t)b * Ss + rb + g) * 2048;
    size_t r1 = ((size_t)b * Ss + rb + 8 + g) * 2048;
#pragma unroll
    for (int nt = 0; nt < 8; nt++) {
        int col = gp * 64 + nt * 8 + t * 2;
        *(uint32_t*)&g_af[r0 + col] = packh(oac[nt][0] * i0, oac[nt][1] * i0);
        *(uint32_t*)&g_af[r1 + col] = packh(oac[nt][2] * i1, oac[nt][3] * i1);
    }
}

// ---------------- launch ---------------------------------------------------
extern "C" void kernel_launch(void* const* d_in, const int* in_sizes, int n_in,
                              void* d_out, int out_size)
{
    const float* x  = (const float*)d_in[0];
    const float* wq = (const float*)d_in[1];
    const float* wk = (const float*)d_in[2];
    const float* wv = (const float*)d_in[3];
    const float* wo = (const float*)d_in[4];
    const float* qn = (const float*)d_in[5];
    const float* kn = (const float*)d_in[6];
    const int* pos  = (const int*)d_in[7];
    float* out = (float*)d_out;

    unsigned short *xh, *wh, *oh, *af;
    cudaGetSymbolAddress((void**)&xh, g_xh);
    cudaGetSymbolAddress((void**)&wh, g_wh);
    cudaGetSymbolAddress((void**)&oh, g_oh);
    cudaGetSymbolAddress((void**)&af, g_af);

    cudaFuncSetAttribute(qkv_mma,  cudaFuncAttributeMaxDynamicSharedMemorySize, GEMM_SMEM);
    cudaFuncSetAttribute(gemm_mma, cudaFuncAttributeMaxDynamicSharedMemorySize, GEMM_SMEM);
    cudaFuncSetAttribute(attn_mma, cudaFuncAttributeMaxDynamicSharedMemorySize, ATT_SMEM);

    convert_all<<<18432, 256>>>((const float4*)x, (const float4*)wq,
                                (const float4*)wk, (const float4*)wv,
                                (const float4*)wo,
                                (uint2*)xh, (uint2*)wh, (uint2*)oh);

    qkv_mma<<<dim3(24, 32), 512, GEMM_SMEM>>>(xh, wh, qn, kn, pos);
    attn_mma<<<dim3(64, 16), 256, ATT_SMEM>>>();
    gemm_mma<<<dim3(16, 32), 512, GEMM_SMEM>>>(af, oh, out, Dd, Dd);
}

// round 11
// speedup vs baseline: 6.6472x; 1.1691x over previous
#include <cuda_runtime.h>
#include <cuda_fp16.h>
#include <cstdint>

#define Bb 2
#define Ss 2048
#define Dd 2048
#define KVH 8
#define QPG 4
#define HD 64
#define Mtot (Bb*Ss)            // 4096
#define NQ (KVH*QPG*HD)         // 2048
#define NKV (KVH*HD)            // 512
#define NTOT (NQ + 2*NKV)       // 3072

// ---------------- scratch (module-load static, no runtime allocs) ----------
__device__ __align__(16) unsigned short g_xh[(size_t)Mtot*Dd];    // x fp16
__device__ __align__(16) unsigned short g_wh[(size_t)NTOT*Dd];    // wq|wk|wv fp16
__device__ __align__(16) unsigned short g_oh[(size_t)Dd*NQ];      // wo fp16
__device__ __align__(16) unsigned short g_af[(size_t)Mtot*NQ];    // attn out fp16
__device__ __align__(16) unsigned short g_qh[(size_t)64*Ss*HD];   // [head][s][h]
__device__ __align__(16) unsigned short g_kh[(size_t)16*Ss*HD];   // [bg][s][h]
__device__ __align__(16) unsigned short g_vth[(size_t)16*HD*Ss];  // [bg][h][s]

// ---------------- helpers ---------------------------------------------------
__device__ __forceinline__ uint32_t s2u(const void* p){
    uint32_t a;
    asm("{ .reg .u64 t; cvta.to.shared.u64 t, %1; cvt.u32.u64 %0, t; }":"=r"(a):"l"(p));
    return a;
}
__device__ __forceinline__ void cp16(uint32_t d, const void* g){
    asm volatile("cp.async.cg.shared.global [%0], [%1], 16;" :: "r"(d), "l"(g));
}
__device__ __forceinline__ void ldm4(uint32_t* r, uint32_t addr){
    asm volatile("ldmatrix.sync.aligned.m8n8.x4.shared.b16 {%0,%1,%2,%3}, [%4];"
        : "=r"(r[0]), "=r"(r[1]), "=r"(r[2]), "=r"(r[3]) : "r"(addr));
}
__device__ __forceinline__ void mma16816(float* c, const uint32_t* a, const uint32_t* b){
    asm volatile("mma.sync.aligned.m16n8k16.row.col.f32.f16.f16.f32 "
        "{%0,%1,%2,%3}, {%4,%5,%6,%7}, {%8,%9}, {%0,%1,%2,%3};"
        : "+f"(c[0]), "+f"(c[1]), "+f"(c[2]), "+f"(c[3])
        : "r"(a[0]), "r"(a[1]), "r"(a[2]), "r"(a[3]), "r"(b[0]), "r"(b[1]));
}
__device__ __forceinline__ uint32_t packh(float lo, float hi){
    uint32_t r;
    asm("cvt.rn.f16x2.f32 %0, %1, %2;" : "=r"(r) : "f"(hi), "f"(lo));
    return r;
}

// ---------------- one-shot fp32 -> fp16 convert of all 5 tensors -----------
__global__ __launch_bounds__(256) void convert_all(
    const float4* __restrict__ x,  const float4* __restrict__ wq,
    const float4* __restrict__ wk, const float4* __restrict__ wv,
    const float4* __restrict__ wo,
    uint2* __restrict__ xh, uint2* __restrict__ wh, uint2* __restrict__ oh)
{
    int i = blockIdx.x*blockDim.x + threadIdx.x;
    const float4* s; uint2* d; int off;
    if (i < 2097152)      { s = x;  d = xh;           off = i; }
    else if (i < 3145728) { s = wq; d = wh;           off = i - 2097152; }
    else if (i < 3407872) { s = wk; d = wh + 1048576; off = i - 3145728; }
    else if (i < 3670016) { s = wv; d = wh + 1310720; off = i - 3407872; }
    else if (i < 4718592) { s = wo; d = oh;           off = i - 3670016; }
    else return;
    float4 v = s[off];
    d[off] = make_uint2(packh(v.x, v.y), packh(v.z, v.w));
}

// ---------------- shared GEMM tile constants -------------------------------
#define T_ELEMS (128*40)
#define STG_ELEMS (2*T_ELEMS)
#define GEMM_SMEM (3*STG_ELEMS*2)   // 61440 bytes

// Common mainloop for 256-thread / 8-warp (4x2) GEMM, warp tile 32x64.
// acc[2][8][4]; wm = wid>>1 (0..3), wn = wid&1 (0..1).
#define GEMM_MAINLOOP(Aptr, Bptr, Kd)                                          \
    const int lrow = tid >> 1, lc2 = (tid & 1) * 2;                            \
    auto prefetch = [&](int c){                                                \
        unsigned short* s = sm + (c % 3) * STG_ELEMS;                          \
        const int k0 = c << 5;                                                 \
        uint32_t so = lrow * 40 + lc2 * 8;                                     \
        const unsigned short* ga = Aptr + (size_t)(Mb + lrow) * Kd + k0 + lc2 * 8; \
        const unsigned short* gb = Bptr + (size_t)(Nb + lrow) * Kd + k0 + lc2 * 8; \
        cp16(s2u(s + so),               ga);                                   \
        cp16(s2u(s + so + 8),           ga + 8);                               \
        cp16(s2u(s + T_ELEMS + so),     gb);                                   \
        cp16(s2u(s + T_ELEMS + so + 8), gb + 8);                               \
        asm volatile("cp.async.commit_group;" ::: "memory");                   \
    };                                                                         \
    const int a_row = wm*32 + ((lane>>3)&1)*8 + (lane&7);                      \
    const int a_kof = (lane>>4)*8;                                             \
    const int b_row = wn*64 + ((lane>>4)&1)*8 + (lane&7);                      \
    const int b_kof = ((lane>>3)&1)*8;                                         \
    prefetch(0);                                                               \
    prefetch(1);                                                               \
    for (int c = 0; c < NC; c++) {                                             \
        if (c + 1 < NC) { asm volatile("cp.async.wait_group 1;" ::: "memory"); }\
        else            { asm volatile("cp.async.wait_group 0;" ::: "memory"); }\
        __syncthreads();                                                       \
        if (c + 2 < NC) prefetch(c + 2);                                       \
        const unsigned short* s = sm + (c % 3) * STG_ELEMS;                    \
        _Pragma("unroll")                                                      \
        for (int kk = 0; kk < 2; kk++) {                                       \
            const int ak = kk*16 + a_kof, bk = kk*16 + b_kof;                  \
            uint32_t ah[2][4], bh[16];                                         \
            _Pragma("unroll")                                                  \
            for (int mt = 0; mt < 2; mt++)                                     \
                ldm4(ah[mt], s2u(s + (a_row + mt*16) * 40 + ak));              \
            _Pragma("unroll")                                                  \
            for (int np = 0; np < 4; np++)                                     \
                ldm4(&bh[np*4], s2u(s + T_ELEMS + (b_row + np*16) * 40 + bk)); \
            _Pragma("unroll")                                                  \
            for (int mt = 0; mt < 2; mt++)                                     \
                _Pragma("unroll")                                              \
                for (int nt = 0; nt < 8; nt++)                                 \
                    mma16816(acc[mt][nt], ah[mt], &bh[nt*2]);                  \
        }                                                                      \
    }

// ---------------- QKV GEMM with fused norm+rope+scatter epilogue -----------
__global__ __launch_bounds__(256, 2) void qkv_mma(
    const unsigned short* __restrict__ A,
    const unsigned short* __restrict__ B,
    const float* __restrict__ qn, const float* __restrict__ kn,
    const int* __restrict__ pos_ids)
{
    extern __shared__ unsigned short sm[];
    const int tid = threadIdx.x, lane = tid & 31, wid = tid >> 5;
    const int wm = wid >> 1, wn = wid & 1;
    const int g = lane >> 2, t = lane & 3;
    const int nb = blockIdx.x, mb = blockIdx.y;
    const int Mb = mb * 128, Nb = nb * 128;
    const int NC = Dd >> 5;   // 64

    float acc[2][8][4];
#pragma unroll
    for (int mt = 0; mt < 2; mt++)
#pragma unroll
        for (int nt = 0; nt < 8; nt++)
#pragma unroll
            for (int r = 0; r < 4; r++) acc[mt][nt][r] = 0.f;

    GEMM_MAINLOOP(A, B, Dd)

    // ---- fused epilogue: stage tile as fp16 in smem ----
    __syncthreads();
    unsigned short* st = sm;                  // [128][132]
#pragma unroll
    for (int mt = 0; mt < 2; mt++) {
        int row = wm*32 + mt*16 + g;
        int colb = wn*64 + t*2;
#pragma unroll
        for (int nt = 0; nt < 8; nt++) {
            *(uint32_t*)&st[(size_t)row    *132 + colb + nt*8] = packh(acc[mt][nt][0], acc[mt][nt][1]);
            *(uint32_t*)&st[(size_t)(row+8)*132 + colb + nt*8] = packh(acc[mt][nt][2], acc[mt][nt][3]);
        }
    }
    __syncthreads();

    if (nb >= 20) {
        // ---- V tiles: transpose-convert to g_vth[bg][h][s] ----
        int c  = tid >> 1;                 // tile col 0..127
        int rh = (tid & 1) * 64;           // row half
        int vcol = nb*128 + c - 2560;      // 0..511
        int kvg = vcol >> 6, h = vcol & 63;
        int m0 = Mb + rh;
        int b = m0 >> 11, s0 = m0 & 2047;
        unsigned short* dst = g_vth + ((size_t)(b*KVH + kvg)*HD + h)*Ss + s0;
#pragma unroll
        for (int i0 = 0; i0 < 64; i0 += 8) {
            uint32_t p[4];
#pragma unroll
            for (int j = 0; j < 4; j++) {
                unsigned short va = st[(size_t)(rh + i0 + 2*j    )*132 + c];
                unsigned short vb = st[(size_t)(rh + i0 + 2*j + 1)*132 + c];
                p[j] = (uint32_t)va | ((uint32_t)vb << 16);
            }
            *(uint4*)(dst + i0) = make_uint4(p[0], p[1], p[2], p[3]);
        }
    } else {
        // ---- Q/K tiles: per-thread row-head rmsnorm + rope ----
        int row = tid & 127, hd = (tid >> 7) & 1;
        int m = Mb + row, b = m >> 11, s = m & 2047;
        uint32_t v2[32];
#pragma unroll
        for (int j = 0; j < 32; j++)
            v2[j] = *(uint32_t*)&st[(size_t)row*132 + hd*64 + j*2];
        float ssum = 0.f;
#pragma unroll
        for (int j = 0; j < 32; j++) {
            float2 f = __half22float2(*(__half2*)&v2[j]);
            ssum += f.x*f.x + f.y*f.y;
        }
        float inv = rsqrtf(ssum * (1.f/64.f) + 1e-5f);
        const float* w = (nb < 16) ? qn : kn;
        float pos = (float)pos_ids[s];
        unsigned short* dst;
        if (nb < 16) {
            int qh = nb*2 + hd;
            dst = g_qh + ((size_t)(b*32 + qh)*Ss + s)*HD;
        } else {
            int kh = (nb - 16)*2 + hd;
            dst = g_kh + ((size_t)(b*KVH + kh)*Ss + s)*HD;
        }
        uint32_t outp[32];
#pragma unroll
        for (int j = 0; j < 16; j++) {
            float2 lo2 = __half22float2(*(__half2*)&v2[j]);      // dims 2j, 2j+1
            float2 hi2 = __half22float2(*(__half2*)&v2[j+16]);   // dims 2j+32, 2j+33
            float x1a = lo2.x * inv * w[2*j];
            float x1b = lo2.y * inv * w[2*j+1];
            float x2a = hi2.x * inv * w[2*j+32];
            float x2b = hi2.y * inv * w[2*j+33];
            float o1a = x1a, o1b = x1b, o2a = x2a, o2b = x2b;
            if (j < 8) {   // dims < 16 rotate
                float fA = pos * exp2f(-0.625f * (float)(2*j));
                float fB = pos * exp2f(-0.625f * (float)(2*j+1));
                float snA = sinf(fA), csA = cosf(fA);
                float snB = sinf(fB), csB = cosf(fB);
                o1a = x1a*csA - x2a*snA;  o2a = x2a*csA + x1a*snA;
                o1b = x1b*csB - x2b*snB;  o2b = x2b*csB + x1b*snB;
            }
            outp[j]      = packh(o1a, o1b);
            outp[j + 16] = packh(o2a, o2b);
        }
#pragma unroll
        for (int i0 = 0; i0 < 32; i0 += 4)
            *(uint4*)(dst + i0*2) = make_uint4(outp[i0], outp[i0+1], outp[i0+2], outp[i0+3]);
    }
}

// ---------------- generic HMMA GEMM (out-projection) -----------------------
__global__ __launch_bounds__(256, 2) void gemm_mma(
    const unsigned short* __restrict__ A,
    const unsigned short* __restrict__ B,
    float* __restrict__ C, int Kd, int ldc)
{
    extern __shared__ unsigned short sm[];
    const int tid = threadIdx.x, lane = tid & 31, wid = tid >> 5;
    const int wm = wid >> 1, wn = wid & 1;
    const int g = lane >> 2, t = lane & 3;
    const int Mb = blockIdx.y * 128, Nb = blockIdx.x * 128;
    const int NC = Kd >> 5;

    float acc[2][8][4];
#pragma unroll
    for (int mt = 0; mt < 2; mt++)
#pragma unroll
        for (int nt = 0; nt < 8; nt++)
#pragma unroll
            for (int r = 0; r < 4; r++) acc[mt][nt][r] = 0.f;

    GEMM_MAINLOOP(A, B, Kd)

#pragma unroll
    for (int mt = 0; mt < 2; mt++) {
        int row = Mb + wm*32 + mt*16 + g;
#pragma unroll
        for (int nt = 0; nt < 8; nt++) {
            int col = Nb + wn*64 + nt*8 + t*2;
            *(float2*)&C[(size_t)row * ldc + col] =
                make_float2(acc[mt][nt][0], acc[mt][nt][1]);
            *(float2*)&C[(size_t)(row + 8) * ldc + col] =
                make_float2(acc[mt][nt][2], acc[mt][nt][3]);
        }
    }
}

// ---------------- MMA flash attention (fp16 1-term) ------------------------
#define QT (128*72)
#define KT (64*72)
#define AST (2*KT)
#define ATT_SMEM ((QT + 2*AST)*2)

__global__ __launch_bounds__(256, 2) void attn_mma()
{
    extern __shared__ unsigned short sm[];
    const int tid = threadIdx.x, lane = tid & 31, wm = tid >> 5;
    const int g = lane >> 2, t = lane & 3;
    const int head = blockIdx.x;
    const int qb = 15 - (int)blockIdx.y;
    const int b = head >> 5, gp = head & 31, kvg = gp >> 2;
    const int rb = qb * 128 + wm * 16;

    const unsigned short* Qh = g_qh + ((size_t)head * Ss + qb * 128) * HD;
    const unsigned short* Kh = g_kh + (size_t)(b * KVH + kvg) * Ss * HD;
    const unsigned short* Vth = g_vth + (size_t)(b * KVH + kvg) * HD * Ss;

    unsigned short* QH = sm;

    {
        int row = tid >> 1, cbq = (tid & 1) * 4;
#pragma unroll
        for (int c = cbq; c < cbq + 4; c++) {
            uint32_t so = row * 72 + c * 8;
            cp16(s2u(QH + so), Qh + row * 64 + c * 8);
        }
        asm volatile("cp.async.commit_group;" ::: "memory");
    }

    auto prefetchKV = [&](int kt){
        unsigned short* st = sm + QT + (kt & 1) * AST;
        int row = tid >> 2, cb2 = (tid & 3) * 2;
#pragma unroll
        for (int c = cb2; c < cb2 + 2; c++) {
            uint32_t so = row * 72 + c * 8;
            cp16(s2u(st +      so), Kh  + (size_t)(kt * 64 + row) * HD + c * 8);
            cp16(s2u(st + KT + so), Vth + (size_t)row * Ss + kt * 64 + c * 8);
        }
        asm volatile("cp.async.commit_group;" ::: "memory");
    };

    prefetchKV(0);

    const int ktmax = 2 * qb + 1;
    float m0 = -1e30f, m1 = -1e30f, l0 = 0.f, l1 = 0.f;
    float oac[8][4];
#pragma unroll
    for (int nt = 0; nt < 8; nt++)
#pragma unroll
        for (int r = 0; r < 4; r++) oac[nt][r] = 0.f;
    uint32_t qfh[4][4];

    const int n_row = ((lane>>4)&1)*8 + (lane&7);
    const int n_kof = ((lane>>3)&1)*8;

    for (int kt = 0; kt <= ktmax; kt++) {
        if (kt < ktmax) {
            prefetchKV(kt + 1);
            asm volatile("cp.async.wait_group 1;" ::: "memory");
        } else {
            asm volatile("cp.async.wait_group 0;" ::: "memory");
        }
        __syncthreads();

        if (kt == 0) {
            const int qa_row = wm*16 + ((lane>>3)&1)*8 + (lane&7);
            const int qa_kof = (lane>>4)*8;
#pragma unroll
            for (int ks = 0; ks < 4; ks++)
                ldm4(qfh[ks], s2u(QH + qa_row * 72 + ks*16 + qa_kof));
        }

        if (kt * 64 <= rb + 15) {
            const unsigned short* KH = sm + QT + (kt & 1) * AST;
            const unsigned short* VH = KH + KT;

            float sc[8][4];
#pragma unroll
            for (int nt = 0; nt < 8; nt++)
#pragma unroll
                for (int r = 0; r < 4; r++) sc[nt][r] = 0.f;
#pragma unroll
            for (int ks = 0; ks < 4; ks++) {
                uint32_t bh[16];
#pragma unroll
                for (int np = 0; np < 4; np++)
                    ldm4(&bh[np*4], s2u(KH + (np*16 + n_row) * 72 + ks*16 + n_kof));
#pragma unroll
                for (int nt = 0; nt < 8; nt++)
                    mma16816(sc[nt], qfh[ks], &bh[nt*2]);
            }

            const bool needmask = (kt * 64 + 63 > rb);
#pragma unroll
            for (int nt = 0; nt < 8; nt++) {
#pragma unroll
                for (int r = 0; r < 4; r++) {
                    float d = sc[nt][r];
                    float z = d * 0.0025f, z2 = z * z;
                    float pq = 1.f + z2*(-0.33333334f + z2*(0.13333334f - z2*0.05396825f));
                    float v = d * 0.125f * pq;
                    if (needmask) {
                        int col = kt*64 + nt*8 + (t<<1) + (r & 1);
                        int row = rb + g + ((r >> 1) << 3);
                        if (col > row) v = -1e30f;
                    }
                    sc[nt][r] = v;
                }
            }

            float tm0 = -1e30f, tm1 = -1e30f;
#pragma unroll
            for (int nt = 0; nt < 8; nt++) {
                tm0 = fmaxf(tm0, fmaxf(sc[nt][0], sc[nt][1]));
                tm1 = fmaxf(tm1, fmaxf(sc[nt][2], sc[nt][3]));
            }
            tm0 = fmaxf(tm0, __shfl_xor_sync(0xffffffffu, tm0, 1));
            tm0 = fmaxf(tm0, __shfl_xor_sync(0xffffffffu, tm0, 2));
            tm1 = fmaxf(tm1, __shfl_xor_sync(0xffffffffu, tm1, 1));
            tm1 = fmaxf(tm1, __shfl_xor_sync(0xffffffffu, tm1, 2));
            float nm0 = fmaxf(m0, tm0), nm1 = fmaxf(m1, tm1);
            float a0 = __expf(m0 - nm0), a1 = __expf(m1 - nm1);
            m0 = nm0; m1 = nm1;
            float rs0 = 0.f, rs1 = 0.f;
#pragma unroll
            for (int nt = 0; nt < 8; nt++) {
                sc[nt][0] = __expf(sc[nt][0] - nm0);
                sc[nt][1] = __expf(sc[nt][1] - nm0);
                sc[nt][2] = __expf(sc[nt][2] - nm1);
                sc[nt][3] = __expf(sc[nt][3] - nm1);
                rs0 += sc[nt][0] + sc[nt][1];
                rs1 += sc[nt][2] + sc[nt][3];
            }
            rs0 += __shfl_xor_sync(0xffffffffu, rs0, 1);
            rs0 += __shfl_xor_sync(0xffffffffu, rs0, 2);
            rs1 += __shfl_xor_sync(0xffffffffu, rs1, 1);
            rs1 += __shfl_xor_sync(0xffffffffu, rs1, 2);
            l0 = l0 * a0 + rs0;
            l1 = l1 * a1 + rs1;
#pragma unroll
            for (int nt = 0; nt < 8; nt++) {
                oac[nt][0] *= a0; oac[nt][1] *= a0;
                oac[nt][2] *= a1; oac[nt][3] *= a1;
            }

#pragma unroll
            for (int ks = 0; ks < 4; ks++) {
                uint32_t pha[4];
                pha[0] = packh(sc[2*ks][0],   sc[2*ks][1]);
                pha[1] = packh(sc[2*ks][2],   sc[2*ks][3]);
                pha[2] = packh(sc[2*ks+1][0], sc[2*ks+1][1]);
                pha[3] = packh(sc[2*ks+1][2], sc[2*ks+1][3]);
                uint32_t vh[16];
#pragma unroll
                for (int np = 0; np < 4; np++)
                    ldm4(&vh[np*4], s2u(VH + (np*16 + n_row) * 72 + ks*16 + n_kof));
#pragma unroll
                for (int nt = 0; nt < 8; nt++)
                    mma16816(oac[nt], pha, &vh[nt*2]);
            }
        }
        __syncthreads();
    }

    float i0 = 1.f / l0, i1 = 1.f / l1;
    size_t r0 = ((size_t)b * Ss + rb + g) * 2048;
    size_t r1 = ((size_t)b * Ss + rb + 8 + g) * 2048;
#pragma unroll
    for (int nt = 0; nt < 8; nt++) {
        int col = gp * 64 + nt * 8 + t * 2;
        *(uint32_t*)&g_af[r0 + col] = packh(oac[nt][0] * i0, oac[nt][1] * i0);
        *(uint32_t*)&g_af[r1 + col] = packh(oac[nt][2] * i1, oac[nt][3] * i1);
    }
}

// ---------------- launch ---------------------------------------------------
extern "C" void kernel_launch(void* const* d_in, const int* in_sizes, int n_in,
                              void* d_out, int out_size)
{
    const float* x  = (const float*)d_in[0];
    const float* wq = (const float*)d_in[1];
    const float* wk = (const float*)d_in[2];
    const float* wv = (const float*)d_in[3];
    const float* wo = (const float*)d_in[4];
    const float* qn = (const float*)d_in[5];
    const float* kn = (const float*)d_in[6];
    const int* pos  = (const int*)d_in[7];
    float* out = (float*)d_out;

    unsigned short *xh, *wh, *oh, *af;
    cudaGetSymbolAddress((void**)&xh, g_xh);
    cudaGetSymbolAddress((void**)&wh, g_wh);
    cudaGetSymbolAddress((void**)&oh, g_oh);
    cudaGetSymbolAddress((void**)&af, g_af);

    cudaFuncSetAttribute(qkv_mma,  cudaFuncAttributeMaxDynamicSharedMemorySize, GEMM_SMEM);
    cudaFuncSetAttribute(gemm_mma, cudaFuncAttributeMaxDynamicSharedMemorySize, GEMM_SMEM);
    cudaFuncSetAttribute(attn_mma, cudaFuncAttributeMaxDynamicSharedMemorySize, ATT_SMEM);

    convert_all<<<18432, 256>>>((const float4*)x, (const float4*)wq,
                                (const float4*)wk, (const float4*)wv,
                                (const float4*)wo,
                                (uint2*)xh, (uint2*)wh, (uint2*)oh);

    qkv_mma<<<dim3(24, 32), 256, GEMM_SMEM>>>(xh, wh, qn, kn, pos);
    attn_mma<<<dim3(64, 16), 256, ATT_SMEM>>>();
    gemm_mma<<<dim3(16, 32), 256, GEMM_SMEM>>>(af, oh, out, Dd, Dd);
}